// round 10
// baseline (speedup 1.0000x reference)
#include <cuda_runtime.h>
#include <cuda_bf16.h>
#include <math.h>
#include <stdint.h>

#define S_LEN 2048
#define E_DIM 1024
#define N_HEADS 16
#define HD 64
#define BATCH 2
#define M_ROWS 4096
#define SCALE_Q 0.18033688011112042f   // 0.125 * log2(e)

// ---------------- scratch ---------------------------------------------------
__device__ __align__(256) float g_cos[S_LEN * 32];
__device__ __align__(256) float g_sin[S_LEN * 32];
__device__ __align__(256) float g_bias[3 * E_DIM];
__device__ __align__(256) float g_xscale[M_ROWS];
__device__ __align__(256) float g_wqscale[3][E_DIM];
__device__ __align__(256) float g_wqinv[3][E_DIM];
__device__ __align__(256) char g_xq1[(size_t)M_ROWS * E_DIM];
__device__ __align__(256) char g_xq0[(size_t)M_ROWS * E_DIM];
__device__ __align__(256) char g_wq1[3][(size_t)E_DIM * E_DIM];  // [N][K]
__device__ __align__(256) char g_wq0[3][(size_t)E_DIM * E_DIM];
__device__ __align__(256) __nv_bfloat16 g_chi[(size_t)M_ROWS * E_DIM];
__device__ __align__(256) __nv_bfloat16 g_clo[(size_t)M_ROWS * E_DIM];
__device__ __align__(256) __nv_bfloat16 g_qhi[(size_t)M_ROWS * E_DIM];
__device__ __align__(256) __nv_bfloat16 g_qlo[(size_t)M_ROWS * E_DIM];
__device__ __align__(256) __nv_bfloat16 g_khi[(size_t)M_ROWS * E_DIM];
__device__ __align__(256) __nv_bfloat16 g_klo[(size_t)M_ROWS * E_DIM];
__device__ __align__(256) __nv_bfloat16 g_vhi[(size_t)M_ROWS * E_DIM];
__device__ __align__(256) __nv_bfloat16 g_vlo[(size_t)M_ROWS * E_DIM];
__device__ __align__(256) __nv_bfloat16 g_wthi[(size_t)E_DIM * E_DIM];  // Wo^T hi
__device__ __align__(256) __nv_bfloat16 g_wtlo[(size_t)E_DIM * E_DIM];  // Wo^T lo

// ---------------- helpers ---------------------------------------------------
__device__ __forceinline__ uint32_t smem_u32(const void* p) {
    uint32_t a;
    asm("{ .reg .u64 t; cvta.to.shared.u64 t, %1; cvt.u32.u64 %0, t; }"
        : "=r"(a) : "l"(p));
    return a;
}
__device__ __forceinline__ void ldmatrix_x4(uint32_t* r, uint32_t addr) {
    asm volatile("ldmatrix.sync.aligned.m8n8.x4.shared.b16 {%0,%1,%2,%3}, [%4];"
                 : "=r"(r[0]), "=r"(r[1]), "=r"(r[2]), "=r"(r[3]) : "r"(addr));
}
__device__ __forceinline__ void ldmatrix_x4_trans(uint32_t* r, uint32_t addr) {
    asm volatile("ldmatrix.sync.aligned.m8n8.x4.trans.shared.b16 {%0,%1,%2,%3}, [%4];"
                 : "=r"(r[0]), "=r"(r[1]), "=r"(r[2]), "=r"(r[3]) : "r"(addr));
}
__device__ __forceinline__ void mma16816(float* c, const uint32_t* a, const uint32_t* b) {
    asm("mma.sync.aligned.m16n8k16.row.col.f32.bf16.bf16.f32 "
        "{%0,%1,%2,%3}, {%4,%5,%6,%7}, {%8,%9}, {%0,%1,%2,%3};"
        : "+f"(c[0]), "+f"(c[1]), "+f"(c[2]), "+f"(c[3])
        : "r"(a[0]), "r"(a[1]), "r"(a[2]), "r"(a[3]), "r"(b[0]), "r"(b[1]));
}
__device__ __forceinline__ void imma16832(int* c, const uint32_t* a, const uint32_t* b) {
    asm("mma.sync.aligned.m16n8k32.row.col.s32.s8.s8.s32 "
        "{%0,%1,%2,%3}, {%4,%5,%6,%7}, {%8,%9}, {%0,%1,%2,%3};"
        : "+r"(c[0]), "+r"(c[1]), "+r"(c[2]), "+r"(c[3])
        : "r"(a[0]), "r"(a[1]), "r"(a[2]), "r"(a[3]), "r"(b[0]), "r"(b[1]));
}
__device__ __forceinline__ void cp_async16(uint32_t dst, const void* src) {
    asm volatile("cp.async.cg.shared.global [%0], [%1], 16;" :: "r"(dst), "l"(src));
}
__device__ __forceinline__ float ex2(float x) {
    float y;
    asm("ex2.approx.f32 %0, %1;" : "=f"(y) : "f"(x));
    return y;
}
__device__ __forceinline__ void split2(float x, float y, uint32_t& h, uint32_t& l) {
    __nv_bfloat162 hb = __floats2bfloat162_rn(x, y);
    float2 hf = __bfloat1622float2(hb);
    __nv_bfloat162 lb = __floats2bfloat162_rn(x - hf.x, y - hf.y);
    h = *(uint32_t*)&hb;
    l = *(uint32_t*)&lb;
}
// int -> (hi7, lo7) split: q = a1*128 + a0, a1 in [-64,64], a0 in [-64,63]
__device__ __forceinline__ void qsplit(int q, int& a1, int& a0) {
    a1 = (q + 64) >> 7;
    a0 = q - (a1 << 7);
}

// ---------------------------------------------------------------------------
__global__ void rope_table_kernel(const float* __restrict__ bq,
                                  const float* __restrict__ bk,
                                  const float* __restrict__ bv) {
    int i = blockIdx.x * blockDim.x + threadIdx.x;
    if (i < 3 * E_DIM) {
        const float* b = (i < E_DIM) ? bq : (i < 2 * E_DIM) ? bk : bv;
        g_bias[i] = b[i & (E_DIM - 1)];
    }
    if (i >= S_LEN * 32) return;
    int s = i >> 5, j = i & 31;
    float inv = (float)pow(10000.0, -(double)j / 32.0);
    float th = (float)s * inv;
    g_cos[i] = cosf(th);
    g_sin[i] = sinf(th);
}

// x row quantization: per-row absmax -> int8 hi/lo pair
__global__ void xquant_kernel(const float* __restrict__ x) {
    __shared__ float red[8];
    const int row = blockIdx.x, tid = threadIdx.x;
    const int lane = tid & 31, wid = tid >> 5;
    float4 v = *(const float4*)(x + (size_t)row * E_DIM + tid * 4);
    float m = fmaxf(fmaxf(fabsf(v.x), fabsf(v.y)), fmaxf(fabsf(v.z), fabsf(v.w)));
#pragma unroll
    for (int off = 16; off >= 1; off >>= 1)
        m = fmaxf(m, __shfl_xor_sync(0xffffffffu, m, off));
    if (lane == 0) red[wid] = m;
    __syncthreads();
    float mx = red[0];
#pragma unroll
    for (int i = 1; i < 8; i++) mx = fmaxf(mx, red[i]);
    mx = fmaxf(mx, 1e-30f);
    if (tid == 0) g_xscale[row] = mx / 8191.0f;
    const float inv = 8191.0f / mx;
    int q[4];
    q[0] = __float2int_rn(v.x * inv);
    q[1] = __float2int_rn(v.y * inv);
    q[2] = __float2int_rn(v.z * inv);
    q[3] = __float2int_rn(v.w * inv);
    uint32_t w1 = 0, w0 = 0;
#pragma unroll
    for (int j = 0; j < 4; j++) {
        int a1, a0;
        qsplit(q[j], a1, a0);
        w1 |= (uint32_t)(a1 & 255) << (8 * j);
        w0 |= (uint32_t)(a0 & 255) << (8 * j);
    }
    *(uint32_t*)(g_xq1 + (size_t)row * E_DIM + tid * 4) = w1;
    *(uint32_t*)(g_xq0 + (size_t)row * E_DIM + tid * 4) = w0;
}

// per-output-column absmax of W[K][N] for z = 0..2
__global__ void wcolmax_kernel(const float* __restrict__ W0,
                               const float* __restrict__ W1,
                               const float* __restrict__ W2) {
    __shared__ float sm[256];
    const float* Ws[3] = {W0, W1, W2};
    const float* W = Ws[blockIdx.y];
    const int n0 = blockIdx.x * 64;
    const int tid = threadIdx.x;
    const int c = tid & 63, seg = tid >> 6;
    float m = 0.f;
    for (int k = seg; k < E_DIM; k += 4)
        m = fmaxf(m, fabsf(W[(size_t)k * E_DIM + n0 + c]));
    sm[tid] = m;
    __syncthreads();
    if (tid < 64) {
        float mx = fmaxf(fmaxf(sm[tid], sm[tid + 64]), fmaxf(sm[tid + 128], sm[tid + 192]));
        mx = fmaxf(mx, 1e-30f);
        g_wqscale[blockIdx.y][n0 + tid] = mx / 8191.0f;
        g_wqinv[blockIdx.y][n0 + tid] = 8191.0f / mx;
    }
}

// transpose-quantize W[K][N] -> wq1/wq0 [N][K] int8 (z = 0..2)
__global__ void wquant_transpose_kernel(const float* __restrict__ W0,
                                        const float* __restrict__ W1,
                                        const float* __restrict__ W2) {
    __shared__ float t[32][33];
    const float* Ws[3] = {W0, W1, W2};
    const int z = blockIdx.z;
    const float* W = Ws[z];
    int bx = blockIdx.x, by = blockIdx.y;
    int tid = threadIdx.x;
#pragma unroll
    for (int it = 0; it < 4; it++) {
        int idx = tid + it * 256;
        int r = idx >> 5, c = idx & 31;
        t[r][c] = W[(size_t)(by * 32 + r) * E_DIM + bx * 32 + c];
    }
    __syncthreads();
#pragma unroll
    for (int it = 0; it < 4; it++) {
        int idx = tid + it * 256;
        int r = idx >> 5, c = idx & 31;
        int n = bx * 32 + r;
        float inv = g_wqinv[z][n];
        int q = __float2int_rn(t[c][r] * inv);
        int a1, a0;
        qsplit(q, a1, a0);
        size_t o = (size_t)n * E_DIM + by * 32 + c;
        g_wq1[z][o] = (char)a1;
        g_wq0[z][o] = (char)a0;
    }
}

// bf16 split transpose for Wo only
__global__ void cvt_transpose_o_kernel(const float* __restrict__ W) {
    __shared__ float t[32][33];
    int bx = blockIdx.x, by = blockIdx.y;
    int tid = threadIdx.x;
#pragma unroll
    for (int it = 0; it < 4; it++) {
        int idx = tid + it * 256;
        int r = idx >> 5, c = idx & 31;
        t[r][c] = W[(size_t)(by * 32 + r) * E_DIM + bx * 32 + c];
    }
    __syncthreads();
#pragma unroll
    for (int it = 0; it < 4; it++) {
        int idx = tid + it * 256;
        int r = idx >> 5, c = idx & 31;
        float x = t[c][r];
        __nv_bfloat16 h = __float2bfloat16(x);
        size_t o = (size_t)(bx * 32 + r) * E_DIM + by * 32 + c;
        g_wthi[o] = h;
        g_wtlo[o] = __float2bfloat16(x - __bfloat162float(h));
    }
}

// ---------------------------------------------------------------------------
// INT8 fixed-point QKV GEMM. CTA 128x128, BK=128 bytes (4 k32 steps),
// 8 warps (4m x 2n), warp tile 32x64.
// acc = sA*sB*(16384*sum(A1B1) + 128*sum(A1B0 + A0B1))   (A0B0 dropped)
// ---------------------------------------------------------------------------
#define QA_TB (128 * 144)     // 18432: 128 rows * (128 + 16 pad) bytes
#define QBUF (4 * QA_TB)      // 73728
#define QSMEM (2 * QBUF)      // 147456
#define QNCHUNK 8

__device__ __forceinline__ void qload_chunk(
    const char* __restrict__ A1, const char* __restrict__ A0,
    const char* __restrict__ B1, const char* __restrict__ B0,
    int m0, int n0, int k0, uint32_t st, int tid) {
    const char* srcs[4] = {A1, A0, B1, B0};
    int r0s[4] = {m0, m0, n0, n0};
#pragma unroll
    for (int tno = 0; tno < 4; tno++) {
        const char* src = srcs[tno];
        int row0 = r0s[tno];
#pragma unroll
        for (int it = 0; it < 4; it++) {
            int idx = tid + it * 256;            // 0..1023
            int r = idx >> 3, seg = idx & 7;
            cp_async16(st + tno * QA_TB + (uint32_t)(r * 144 + seg * 16),
                       src + (size_t)(row0 + r) * E_DIM + k0 + seg * 16);
        }
    }
}

__global__ __launch_bounds__(256)
void tgemm_qkv_kernel() {
    extern __shared__ __align__(1024) char dsm[];
    const uint32_t sbase = smem_u32(dsm);
    const int tid = threadIdx.x;
    const int wid = tid >> 5, lane = tid & 31;
    const int wm = wid & 3, wn = wid >> 2;
    const int g = lane >> 2, tg = lane & 3;
    const int m0 = blockIdx.y << 7, n0 = blockIdx.x << 7;
    const int z = blockIdx.z;

    const char* B1p = g_wq1[z];
    const char* B0p = g_wq0[z];
    const float* bias = g_bias + (z << 10);
    __nv_bfloat16* Chi = (z == 0) ? g_qhi : (z == 1) ? g_khi : g_vhi;
    __nv_bfloat16* Clo = (z == 0) ? g_qlo : (z == 1) ? g_klo : g_vlo;

    int acc1[2][8][4] = {};
    int acc2[2][8][4] = {};

    qload_chunk(g_xq1, g_xq0, B1p, B0p, m0, n0, 0, sbase, tid);
    asm volatile("cp.async.commit_group;");

    for (int c = 0; c < QNCHUNK; c++) {
        asm volatile("cp.async.wait_group 0;");
        __syncthreads();
        if (c + 1 < QNCHUNK) {
            qload_chunk(g_xq1, g_xq0, B1p, B0p, m0, n0, (c + 1) << 7,
                        sbase + ((c + 1) & 1) * QBUF, tid);
            asm volatile("cp.async.commit_group;");
        }
        const uint32_t st = sbase + (c & 1) * QBUF;
        const uint32_t A1s = st, A0s = st + QA_TB;
        const uint32_t B1s = st + 2 * QA_TB, B0s = st + 3 * QA_TB;

#pragma unroll
        for (int ks = 0; ks < 4; ks++) {
            uint32_t a1[2][4], a0[2][4];
#pragma unroll
            for (int mt = 0; mt < 2; mt++) {
                int row = wm * 32 + mt * 16 + (lane & 15);
                uint32_t off = (uint32_t)(row * 144 + ks * 32 + ((lane >> 4) << 4));
                ldmatrix_x4(a1[mt], A1s + off);
                ldmatrix_x4(a0[mt], A0s + off);
            }
#pragma unroll
            for (int np = 0; np < 4; np++) {
                uint32_t b1[4], b0[4];
                int row = wn * 64 + np * 16 + ((lane >> 4) << 3) + (lane & 7);
                uint32_t off = (uint32_t)(row * 144 + ks * 32 + (((lane >> 3) & 1) << 4));
                ldmatrix_x4(b1, B1s + off);
                ldmatrix_x4(b0, B0s + off);
#pragma unroll
                for (int half = 0; half < 2; half++)
#pragma unroll
                    for (int mt = 0; mt < 2; mt++)
                        imma16832(acc1[mt][2 * np + half], a1[mt], b1 + 2 * half);
#pragma unroll
                for (int half = 0; half < 2; half++)
#pragma unroll
                    for (int mt = 0; mt < 2; mt++)
                        imma16832(acc2[mt][2 * np + half], a1[mt], b0 + 2 * half);
#pragma unroll
                for (int half = 0; half < 2; half++)
#pragma unroll
                    for (int mt = 0; mt < 2; mt++)
                        imma16832(acc2[mt][2 * np + half], a0[mt], b1 + 2 * half);
            }
        }
    }

    // epilogue: dequant + bias (+ RoPE for Q/K, + SCALE_Q for Q), split-bf16 store
    const int h = (n0 + wn * 64) >> 6;
    float sB[8][2];
#pragma unroll
    for (int nt = 0; nt < 8; nt++) {
        float2 sv = *(const float2*)&g_wqscale[z][n0 + wn * 64 + nt * 8 + tg * 2];
        sB[nt][0] = sv.x;
        sB[nt][1] = sv.y;
    }
#pragma unroll
    for (int mt = 0; mt < 2; mt++) {
#pragma unroll
        for (int h2 = 0; h2 < 2; h2++) {
            int m = m0 + wm * 32 + mt * 16 + g + h2 * 8;
            int bb = m >> 11, s = m & (S_LEN - 1);
            size_t rb = (((size_t)(bb * N_HEADS + h)) * S_LEN + s) << 6;
            float sA = g_xscale[m];
            float vals[8][2];
#pragma unroll
            for (int nt = 0; nt < 8; nt++) {
                int col = nt * 8 + tg * 2;
                float2 bv = *(const float2*)&bias[n0 + wn * 64 + col];
#pragma unroll
                for (int jj = 0; jj < 2; jj++) {
                    float raw = 16384.f * (float)acc1[mt][nt][h2 * 2 + jj] +
                                128.f * (float)acc2[mt][nt][h2 * 2 + jj];
                    vals[nt][jj] = raw * (sA * sB[nt][jj]) + ((jj == 0) ? bv.x : bv.y);
                }
            }
            if (z < 2) {
#pragma unroll
                for (int nt = 0; nt < 4; nt++) {
#pragma unroll
                    for (int jj = 0; jj < 2; jj++) {
                        int d = nt * 8 + tg * 2 + jj;
                        float cth = g_cos[(s << 5) + d];
                        float sth = g_sin[(s << 5) + d];
                        float lo = vals[nt][jj], hi = vals[nt + 4][jj];
                        vals[nt][jj]     = fmaf(lo, cth, -hi * sth);
                        vals[nt + 4][jj] = fmaf(hi, cth,  lo * sth);
                    }
                }
            }
            if (z == 0) {
#pragma unroll
                for (int nt = 0; nt < 8; nt++) {
                    vals[nt][0] *= SCALE_Q;
                    vals[nt][1] *= SCALE_Q;
                }
            }
#pragma unroll
            for (int nt = 0; nt < 8; nt++) {
                uint32_t hv, lv;
                split2(vals[nt][0], vals[nt][1], hv, lv);
                *(uint32_t*)(Chi + rb + nt * 8 + tg * 2) = hv;
                *(uint32_t*)(Clo + rb + nt * 8 + tg * 2) = lv;
            }
        }
    }
}

// ---------------------------------------------------------------------------
// Split-bf16 out-projection GEMM (unchanged from R9). CTA 256x128, BK=64.
// ---------------------------------------------------------------------------
#define A_TB 36864
#define B_TB 18432
#define BUF_BYTES (2 * A_TB + 2 * B_TB)
#define GSMEM (2 * BUF_BYTES)
#define NCHUNK 16

__device__ __forceinline__ void load_chunk_async(
    const __nv_bfloat16* __restrict__ Ahi, const __nv_bfloat16* __restrict__ Alo,
    const __nv_bfloat16* __restrict__ Bhi, const __nv_bfloat16* __restrict__ Blo,
    int m0, int n0, int k0, uint32_t st, int tid) {
#pragma unroll
    for (int it = 0; it < 8; it++) {
        int idx = tid + it * 256;
        int r = idx >> 3, seg = idx & 7;
        uint32_t off = (uint32_t)(r * 144 + seg * 16);
        const size_t go = (size_t)(m0 + r) * E_DIM + k0 + seg * 8;
        cp_async16(st + off, Ahi + go);
        cp_async16(st + A_TB + off, Alo + go);
    }
#pragma unroll
    for (int it = 0; it < 4; it++) {
        int idx = tid + it * 256;
        int r = idx >> 3, seg = idx & 7;
        uint32_t off = (uint32_t)(r * 144 + seg * 16);
        const size_t go = (size_t)(n0 + r) * E_DIM + k0 + seg * 8;
        cp_async16(st + 2 * A_TB + off, Bhi + go);
        cp_async16(st + 2 * A_TB + B_TB + off, Blo + go);
    }
}

__global__ __launch_bounds__(256)
void tgemm_out_kernel(const float* __restrict__ bias, float* __restrict__ C) {
    extern __shared__ __align__(1024) char dsm[];
    const uint32_t sbase = smem_u32(dsm);
    const int tid = threadIdx.x;
    const int wid = tid >> 5, lane = tid & 31;
    const int wm = wid & 3, wn = wid >> 2;
    const int g = lane >> 2, tg = lane & 3;
    const int m0 = blockIdx.y << 8, n0 = blockIdx.x << 7;

    float acc[4][8][4] = {};

    load_chunk_async(g_chi, g_clo, g_wthi, g_wtlo, m0, n0, 0, sbase, tid);
    asm volatile("cp.async.commit_group;");

    for (int c = 0; c < NCHUNK; c++) {
        asm volatile("cp.async.wait_group 0;");
        __syncthreads();
        if (c + 1 < NCHUNK) {
            load_chunk_async(g_chi, g_clo, g_wthi, g_wtlo, m0, n0, (c + 1) << 6,
                             sbase + ((c + 1) & 1) * BUF_BYTES, tid);
            asm volatile("cp.async.commit_group;");
        }
        const uint32_t st = sbase + (c & 1) * BUF_BYTES;
        const uint32_t Ahi_s = st, Alo_s = st + A_TB;
        const uint32_t Bhi_s = st + 2 * A_TB, Blo_s = st + 2 * A_TB + B_TB;

#pragma unroll
        for (int ks = 0; ks < 4; ks++) {
            uint32_t ah[4][4], al[4][4];
#pragma unroll
            for (int mt = 0; mt < 4; mt++) {
                int row = wm * 64 + mt * 16 + (lane & 15);
                int kb = ks * 16 + ((lane >> 4) << 3);
                uint32_t off = (uint32_t)(row * 144 + kb * 2);
                ldmatrix_x4(ah[mt], Ahi_s + off);
                ldmatrix_x4(al[mt], Alo_s + off);
            }
#pragma unroll
            for (int np = 0; np < 4; np++) {
                uint32_t bh[4], bl[4];
                int row = wn * 64 + np * 16 + ((lane >> 4) << 3) + (lane & 7);
                int kb = ks * 16 + (((lane >> 3) & 1) << 3);
                uint32_t off = (uint32_t)(row * 144 + kb * 2);
                ldmatrix_x4(bh, Bhi_s + off);
                ldmatrix_x4(bl, Blo_s + off);
#pragma unroll
                for (int half = 0; half < 2; half++)
#pragma unroll
                    for (int mt = 0; mt < 4; mt++)
                        mma16816(acc[mt][2 * np + half], ah[mt], bh + 2 * half);
#pragma unroll
                for (int half = 0; half < 2; half++)
#pragma unroll
                    for (int mt = 0; mt < 4; mt++)
                        mma16816(acc[mt][2 * np + half], ah[mt], bl + 2 * half);
#pragma unroll
                for (int half = 0; half < 2; half++)
#pragma unroll
                    for (int mt = 0; mt < 4; mt++)
                        mma16816(acc[mt][2 * np + half], al[mt], bh + 2 * half);
            }
        }
    }

#pragma unroll
    for (int mt = 0; mt < 4; mt++) {
#pragma unroll
        for (int h2 = 0; h2 < 2; h2++) {
            int m = m0 + wm * 64 + mt * 16 + g + h2 * 8;
            float* dst = &C[(size_t)m * E_DIM + n0 + wn * 64];
#pragma unroll
            for (int nt = 0; nt < 8; nt++) {
                int col = nt * 8 + tg * 2;
                float2 bv = *(const float2*)&bias[n0 + wn * 64 + col];
                *(float2*)&dst[col] = make_float2(acc[mt][nt][h2 * 2 + 0] + bv.x,
                                                  acc[mt][nt][h2 * 2 + 1] + bv.y);
            }
        }
    }
}

// ---------------------------------------------------------------------------
// Tensorized flash attention (unchanged from R9). Q-tile 128, KV-tile 128.
// ---------------------------------------------------------------------------
#define ATT_Q    0
#define ATT_QL   18432
#define ATT_BUF0 36864
#define ATT_BUFSZ 74240
#define ATT_SMEM (36864 + 2 * ATT_BUFSZ)

__device__ __forceinline__ void attn_issue_kv(
    const __nv_bfloat16* khi, const __nv_bfloat16* klo,
    const __nv_bfloat16* vhi, const __nv_bfloat16* vlo,
    const int* mask, int mask_off, uint32_t sb, int t, int tid) {
    uint32_t bufb = sb + ATT_BUF0 + (t & 1) * ATT_BUFSZ;
    int k0 = t << 7;
    const __nv_bfloat16* srcs[4] = {khi, klo, vhi, vlo};
#pragma unroll
    for (int i = 0; i < 16; i++) {
        int idx = tid + i * 256;
        int arr = idx >> 10;
        int r = (idx >> 3) & 127, seg = idx & 7;
        cp_async16(bufb + arr * 18432 + (uint32_t)(r * 144 + seg * 16),
                   srcs[arr] + (size_t)(k0 + r) * HD + seg * 8);
    }
    if (tid < 32)
        cp_async16(bufb + 73728 + tid * 16, mask + mask_off + k0 + tid * 4);
}

__global__ __launch_bounds__(256)
void attn_kernel(const int* __restrict__ mask) {
    extern __shared__ __align__(1024) char sm_[];
    const uint32_t sb = smem_u32(sm_);
    const int tid = threadIdx.x, w = tid >> 5, lane = tid & 31;
    const int g = lane >> 2, tg = lane & 3;
    const int qt = gridDim.x - 1 - blockIdx.x;
    const int bh = blockIdx.y, bb = bh >> 4, hh = bh & 15;
    const int q0 = qt << 7;
    const size_t base = (size_t)bh * S_LEN * HD;

    {
        const __nv_bfloat16* s0 = g_qhi + base + (size_t)q0 * HD;
        const __nv_bfloat16* s1 = g_qlo + base + (size_t)q0 * HD;
#pragma unroll
        for (int i = 0; i < 8; i++) {
            int idx = tid + i * 256;
            int arr = idx >> 10;
            int r = (idx >> 3) & 127, seg = idx & 7;
            uint4 v = *(const uint4*)((arr ? s1 : s0) + (size_t)r * HD + seg * 8);
            *(uint4*)(sm_ + (arr ? ATT_QL : ATT_Q) + r * 144 + seg * 16) = v;
        }
    }

    const int ntile = qt + 1;
    attn_issue_kv(g_khi + base, g_klo + base, g_vhi + base, g_vlo + base,
                  mask, bb * S_LEN, sb, 0, tid);
    asm volatile("cp.async.commit_group;");
    __syncthreads();

    uint32_t qfh[4][4], qfl[4][4];
    {
        int i = lane & 15;
        int prow = (i < 8) ? (w * 8 + i) : (64 + w * 8 + (i - 8));
        int kb = ((lane >> 4) << 3);
#pragma unroll
        for (int ks = 0; ks < 4; ks++) {
            uint32_t off = (uint32_t)(prow * 144 + (ks * 16 + kb) * 2);
            ldmatrix_x4(qfh[ks], sb + ATT_Q + off);
            ldmatrix_x4(qfl[ks], sb + ATT_QL + off);
        }
    }
    const int row0 = q0 + w * 8 + g;
    const int row1 = q0 + 64 + w * 8 + g;

    float oacc[8][4] = {};
    float l0 = 0.f, l1 = 0.f, mo0 = -1e30f, mo1 = -1e30f;

    for (int t = 0; t < ntile; t++) {
        asm volatile("cp.async.wait_group 0;");
        __syncthreads();
        if (t + 1 < ntile) {
            attn_issue_kv(g_khi + base, g_klo + base, g_vhi + base, g_vlo + base,
                          mask, bb * S_LEN, sb, t + 1, tid);
            asm volatile("cp.async.commit_group;");
        }
        const uint32_t bufb = sb + ATT_BUF0 + (t & 1) * ATT_BUFSZ;
        const int k0 = t << 7;

        float sc[16][4] = {};
#pragma unroll
        for (int ks = 0; ks < 4; ks++) {
#pragma unroll
            for (int ntp = 0; ntp < 8; ntp++) {
                uint32_t kh[4], kl[4];
                int row = ntp * 16 + ((lane >> 4) << 3) + (lane & 7);
                int kb = ks * 16 + (((lane >> 3) & 1) << 3);
                uint32_t off = (uint32_t)(row * 144 + kb * 2);
                ldmatrix_x4(kh, bufb + off);
                ldmatrix_x4(kl, bufb + 18432 + off);
#pragma unroll
                for (int hf = 0; hf < 2; hf++)
                    mma16816(sc[2 * ntp + hf], qfh[ks], kh + 2 * hf);
#pragma unroll
                for (int hf = 0; hf < 2; hf++)
                    mma16816(sc[2 * ntp + hf], qfh[ks], kl + 2 * hf);
#pragma unroll
                for (int hf = 0; hf < 2; hf++)
                    mma16816(sc[2 * ntp + hf], qfl[ks], kh + 2 * hf);
            }
        }

        const int* Ms = (const int*)(sm_ + ATT_BUF0 + (t & 1) * ATT_BUFSZ + 73728);
        uint32_t pb[4];
        pb[0] = __ballot_sync(0xffffffffu, Ms[lane] != 0);
        pb[1] = __ballot_sync(0xffffffffu, Ms[lane + 32] != 0);
        pb[2] = __ballot_sync(0xffffffffu, Ms[lane + 64] != 0);
        pb[3] = __ballot_sync(0xffffffffu, Ms[lane + 96] != 0);
        if ((pb[0] & pb[1] & pb[2] & pb[3]) != 0xffffffffu) {
#pragma unroll
            for (int nt = 0; nt < 16; nt++)
#pragma unroll
                for (int j = 0; j < 2; j++) {
                    int cl = nt * 8 + tg * 2 + j;
                    if (!((pb[cl >> 5] >> (cl & 31)) & 1)) {
                        sc[nt][j] = -1e30f;
                        sc[nt][2 + j] = -1e30f;
                    }
                }
        }
        if (k0 + 127 > row0) {
#pragma unroll
            for (int nt = 0; nt < 16; nt++)
#pragma unroll
                for (int j = 0; j < 2; j++) {
                    int cg = k0 + nt * 8 + tg * 2 + j;
                    if (cg > row0) sc[nt][j] = -1e30f;
                    if (cg > row1) sc[nt][2 + j] = -1e30f;
                }
        }

        float mx0 = -1e30f, mx1 = -1e30f;
#pragma unroll
        for (int nt = 0; nt < 16; nt++) {
            mx0 = fmaxf(mx0, fmaxf(sc[nt][0], sc[nt][1]));
            mx1 = fmaxf(mx1, fmaxf(sc[nt][2], sc[nt][3]));
        }
        mx0 = fmaxf(mx0, __shfl_xor_sync(0xffffffffu, mx0, 1));
        mx0 = fmaxf(mx0, __shfl_xor_sync(0xffffffffu, mx0, 2));
        mx1 = fmaxf(mx1, __shfl_xor_sync(0xffffffffu, mx1, 1));
        mx1 = fmaxf(mx1, __shfl_xor_sync(0xffffffffu, mx1, 2));
        float mn0 = fmaxf(mo0, mx0), mn1 = fmaxf(mo1, mx1);
        float al0 = ex2(mo0 - mn0), al1 = ex2(mo1 - mn1);
        float rs0 = 0.f, rs1 = 0.f;
#pragma unroll
        for (int nt = 0; nt < 16; nt++) {
            sc[nt][0] = ex2(sc[nt][0] - mn0);
            sc[nt][1] = ex2(sc[nt][1] - mn0);
            sc[nt][2] = ex2(sc[nt][2] - mn1);
            sc[nt][3] = ex2(sc[nt][3] - mn1);
            rs0 += sc[nt][0] + sc[nt][1];
            rs1 += sc[nt][2] + sc[nt][3];
        }
        rs0 += __shfl_xor_sync(0xffffffffu, rs0, 1);
        rs0 += __shfl_xor_sync(0xffffffffu, rs0, 2);
        rs1 += __shfl_xor_sync(0xffffffffu, rs1, 1);
        rs1 += __shfl_xor_sync(0xffffffffu, rs1, 2);
        l0 = l0 * al0 + rs0;
        l1 = l1 * al1 + rs1;
        mo0 = mn0; mo1 = mn1;
#pragma unroll
        for (int nt = 0; nt < 8; nt++) {
            oacc[nt][0] *= al0; oacc[nt][1] *= al0;
            oacc[nt][2] *= al1; oacc[nt][3] *= al1;
        }

#pragma unroll
        for (int ks = 0; ks < 8; ks++) {
            uint32_t pa[4], pl[4];
            split2(sc[2 * ks][0], sc[2 * ks][1], pa[0], pl[0]);
            split2(sc[2 * ks][2], sc[2 * ks][3], pa[1], pl[1]);
            split2(sc[2 * ks + 1][0], sc[2 * ks + 1][1], pa[2], pl[2]);
            split2(sc[2 * ks + 1][2], sc[2 * ks + 1][3], pa[3], pl[3]);
#pragma unroll
            for (int dtp = 0; dtp < 4; dtp++) {
                uint32_t vh[4], vl[4];
                int rkv = ks * 16 + ((lane >> 3) & 1) * 8 + (lane & 7);
                int cd = dtp * 16 + (lane >> 4) * 8;
                uint32_t off = (uint32_t)(rkv * 144 + cd * 2);
                ldmatrix_x4_trans(vh, bufb + 36864 + off);
                ldmatrix_x4_trans(vl, bufb + 55296 + off);
#pragma unroll
                for (int hf = 0; hf < 2; hf++)
                    mma16816(oacc[2 * dtp + hf], pa, vh + 2 * hf);
#pragma unroll
                for (int hf = 0; hf < 2; hf++)
                    mma16816(oacc[2 * dtp + hf], pa, vl + 2 * hf);
#pragma unroll
                for (int hf = 0; hf < 2; hf++)
                    mma16816(oacc[2 * dtp + hf], pl, vh + 2 * hf);
            }
        }
    }

    float inv0 = 1.0f / l0, inv1 = 1.0f / l1;
    __nv_bfloat16* dh0 = g_chi + ((size_t)(bb * S_LEN + row0)) * E_DIM + hh * 64;
    __nv_bfloat16* dl0 = g_clo + ((size_t)(bb * S_LEN + row0)) * E_DIM + hh * 64;
    __nv_bfloat16* dh1 = g_chi + ((size_t)(bb * S_LEN + row1)) * E_DIM + hh * 64;
    __nv_bfloat16* dl1 = g_clo + ((size_t)(bb * S_LEN + row1)) * E_DIM + hh * 64;
#pragma unroll
    for (int nt = 0; nt < 8; nt++) {
        int d = nt * 8 + tg * 2;
        uint32_t hv, lv;
        split2(oacc[nt][0] * inv0, oacc[nt][1] * inv0, hv, lv);
        *(uint32_t*)(dh0 + d) = hv;
        *(uint32_t*)(dl0 + d) = lv;
        split2(oacc[nt][2] * inv1, oacc[nt][3] * inv1, hv, lv);
        *(uint32_t*)(dh1 + d) = hv;
        *(uint32_t*)(dl1 + d) = lv;
    }
}

// ---------------------------------------------------------------------------
extern "C" void kernel_launch(void* const* d_in, const int* in_sizes, int n_in,
                              void* d_out, int out_size) {
    const float* x    = (const float*)d_in[0];
    const int*   mask = (const int*)d_in[1];
    const float* Wq   = (const float*)d_in[2];
    const float* bq   = (const float*)d_in[3];
    const float* Wk   = (const float*)d_in[4];
    const float* bk   = (const float*)d_in[5];
    const float* Wv   = (const float*)d_in[6];
    const float* bv   = (const float*)d_in[7];
    const float* Wo   = (const float*)d_in[8];
    const float* bo   = (const float*)d_in[9];
    float* out = (float*)d_out;

    rope_table_kernel<<<(S_LEN * 32 + 255) / 256, 256>>>(bq, bk, bv);
    xquant_kernel<<<M_ROWS, 256>>>(x);
    wcolmax_kernel<<<dim3(E_DIM / 64, 3), 256>>>(Wq, Wk, Wv);
    wquant_transpose_kernel<<<dim3(32, 32, 3), 256>>>(Wq, Wk, Wv);
    cvt_transpose_o_kernel<<<dim3(32, 32), 256>>>(Wo);

    cudaFuncSetAttribute(tgemm_qkv_kernel, cudaFuncAttributeMaxDynamicSharedMemorySize, QSMEM);
    cudaFuncSetAttribute(tgemm_out_kernel, cudaFuncAttributeMaxDynamicSharedMemorySize, GSMEM);
    cudaFuncSetAttribute(attn_kernel, cudaFuncAttributeMaxDynamicSharedMemorySize, ATT_SMEM);

    tgemm_qkv_kernel<<<dim3(E_DIM / 128, M_ROWS / 128, 3), 256, QSMEM>>>();

    attn_kernel<<<dim3(S_LEN / 128, BATCH * N_HEADS), 256, ATT_SMEM>>>(mask);

    tgemm_out_kernel<<<dim3(E_DIM / 128, M_ROWS / 256), 256, GSMEM>>>(bo, out);
}

// round 11
// speedup vs baseline: 1.7783x; 1.7783x over previous
#include <cuda_runtime.h>
#include <cuda_bf16.h>
#include <math.h>
#include <stdint.h>

#define S_LEN 2048
#define E_DIM 1024
#define N_HEADS 16
#define HD 64
#define BATCH 2
#define M_ROWS 4096
#define SCALE_Q 0.18033688011112042f   // 0.125 * log2(e)

// ---------------- scratch ---------------------------------------------------
__device__ __align__(256) float g_cos[S_LEN * 32];
__device__ __align__(256) float g_sin[S_LEN * 32];
__device__ __align__(256) float g_bias[3 * E_DIM];
__device__ __align__(256) __nv_bfloat16 g_xhi[(size_t)M_ROWS * E_DIM];
__device__ __align__(256) __nv_bfloat16 g_xlo[(size_t)M_ROWS * E_DIM];
__device__ __align__(256) __nv_bfloat16 g_chi[(size_t)M_ROWS * E_DIM];
__device__ __align__(256) __nv_bfloat16 g_clo[(size_t)M_ROWS * E_DIM];
__device__ __align__(256) __nv_bfloat16 g_qhi[(size_t)M_ROWS * E_DIM];
__device__ __align__(256) __nv_bfloat16 g_qlo[(size_t)M_ROWS * E_DIM];
__device__ __align__(256) __nv_bfloat16 g_khi[(size_t)M_ROWS * E_DIM];
__device__ __align__(256) __nv_bfloat16 g_klo[(size_t)M_ROWS * E_DIM];
__device__ __align__(256) __nv_bfloat16 g_vhi[(size_t)M_ROWS * E_DIM];
__device__ __align__(256) __nv_bfloat16 g_vlo[(size_t)M_ROWS * E_DIM];
__device__ __align__(256) __nv_bfloat16 g_wthi[4][(size_t)E_DIM * E_DIM];  // [N][K]
__device__ __align__(256) __nv_bfloat16 g_wtlo[4][(size_t)E_DIM * E_DIM];

// ---------------- helpers ---------------------------------------------------
__device__ __forceinline__ uint32_t smem_u32(const void* p) {
    uint32_t a;
    asm("{ .reg .u64 t; cvta.to.shared.u64 t, %1; cvt.u32.u64 %0, t; }"
        : "=r"(a) : "l"(p));
    return a;
}
__device__ __forceinline__ void ldmatrix_x4(uint32_t* r, uint32_t addr) {
    asm volatile("ldmatrix.sync.aligned.m8n8.x4.shared.b16 {%0,%1,%2,%3}, [%4];"
                 : "=r"(r[0]), "=r"(r[1]), "=r"(r[2]), "=r"(r[3]) : "r"(addr));
}
__device__ __forceinline__ void ldmatrix_x4_trans(uint32_t* r, uint32_t addr) {
    asm volatile("ldmatrix.sync.aligned.m8n8.x4.trans.shared.b16 {%0,%1,%2,%3}, [%4];"
                 : "=r"(r[0]), "=r"(r[1]), "=r"(r[2]), "=r"(r[3]) : "r"(addr));
}
__device__ __forceinline__ void mma16816(float* c, const uint32_t* a, const uint32_t* b) {
    asm("mma.sync.aligned.m16n8k16.row.col.f32.bf16.bf16.f32 "
        "{%0,%1,%2,%3}, {%4,%5,%6,%7}, {%8,%9}, {%0,%1,%2,%3};"
        : "+f"(c[0]), "+f"(c[1]), "+f"(c[2]), "+f"(c[3])
        : "r"(a[0]), "r"(a[1]), "r"(a[2]), "r"(a[3]), "r"(b[0]), "r"(b[1]));
}
__device__ __forceinline__ void cp_async16(uint32_t dst, const void* src) {
    asm volatile("cp.async.cg.shared.global [%0], [%1], 16;" :: "r"(dst), "l"(src));
}
__device__ __forceinline__ float ex2(float x) {
    float y;
    asm("ex2.approx.f32 %0, %1;" : "=f"(y) : "f"(x));
    return y;
}
__device__ __forceinline__ void split2(float x, float y, uint32_t& h, uint32_t& l) {
    __nv_bfloat162 hb = __floats2bfloat162_rn(x, y);
    float2 hf = __bfloat1622float2(hb);
    __nv_bfloat162 lb = __floats2bfloat162_rn(x - hf.x, y - hf.y);
    h = *(uint32_t*)&hb;
    l = *(uint32_t*)&lb;
}

// ---------------------------------------------------------------------------
__global__ void rope_table_kernel(const float* __restrict__ bq,
                                  const float* __restrict__ bk,
                                  const float* __restrict__ bv) {
    int i = blockIdx.x * blockDim.x + threadIdx.x;
    if (i < 3 * E_DIM) {
        const float* b = (i < E_DIM) ? bq : (i < 2 * E_DIM) ? bk : bv;
        g_bias[i] = b[i & (E_DIM - 1)];
    }
    if (i >= S_LEN * 32) return;
    int s = i >> 5, j = i & 31;
    float inv = (float)pow(10000.0, -(double)j / 32.0);
    float th = (float)s * inv;
    g_cos[i] = cosf(th);
    g_sin[i] = sinf(th);
}

__global__ void cvt_split_kernel(const float4* __restrict__ src,
                                 __nv_bfloat162* __restrict__ hi,
                                 __nv_bfloat162* __restrict__ lo, int n4) {
    int i = blockIdx.x * blockDim.x + threadIdx.x;
    if (i >= n4) return;
    float4 v = src[i];
    __nv_bfloat162 h01 = __floats2bfloat162_rn(v.x, v.y);
    __nv_bfloat162 h23 = __floats2bfloat162_rn(v.z, v.w);
    float2 f01 = __bfloat1622float2(h01);
    float2 f23 = __bfloat1622float2(h23);
    hi[2 * i] = h01;
    hi[2 * i + 1] = h23;
    lo[2 * i] = __floats2bfloat162_rn(v.x - f01.x, v.y - f01.y);
    lo[2 * i + 1] = __floats2bfloat162_rn(v.z - f23.x, v.w - f23.y);
}

__global__ void cvt_transpose4_kernel(const float* __restrict__ W0,
                                      const float* __restrict__ W1,
                                      const float* __restrict__ W2,
                                      const float* __restrict__ W3) {
    __shared__ float t[32][33];
    const float* Ws[4] = {W0, W1, W2, W3};
    const float* W = Ws[blockIdx.z];
    __nv_bfloat16* thiz = g_wthi[blockIdx.z];
    __nv_bfloat16* tloz = g_wtlo[blockIdx.z];
    int bx = blockIdx.x, by = blockIdx.y;
    int tid = threadIdx.x;
#pragma unroll
    for (int it = 0; it < 4; it++) {
        int idx = tid + it * 256;
        int r = idx >> 5, c = idx & 31;
        t[r][c] = W[(size_t)(by * 32 + r) * E_DIM + bx * 32 + c];
    }
    __syncthreads();
#pragma unroll
    for (int it = 0; it < 4; it++) {
        int idx = tid + it * 256;
        int r = idx >> 5, c = idx & 31;
        float x = t[c][r];
        __nv_bfloat16 h = __float2bfloat16(x);
        size_t o = (size_t)(bx * 32 + r) * E_DIM + by * 32 + c;
        thiz[o] = h;
        tloz[o] = __float2bfloat16(x - __bfloat162float(h));
    }
}

// ---------------------------------------------------------------------------
// Split-bf16 mma.sync GEMM. CTA tile 256x128, BK=64, 8 warps (4x2),
// warp tile 64x64.
// ---------------------------------------------------------------------------
#define A_TB 36864                      // 256 rows * 144 B
#define B_TB 18432                      // 128 rows * 144 B
#define BUF_BYTES (2 * A_TB + 2 * B_TB) // 110592
#define GSMEM (2 * BUF_BYTES)           // 221184
#define NCHUNK 16

__device__ __forceinline__ void load_chunk_async(
    const __nv_bfloat16* __restrict__ Ahi, const __nv_bfloat16* __restrict__ Alo,
    const __nv_bfloat16* __restrict__ Bhi, const __nv_bfloat16* __restrict__ Blo,
    int m0, int n0, int k0, uint32_t st, int tid) {
#pragma unroll
    for (int it = 0; it < 8; it++) {
        int idx = tid + it * 256;            // 0..2047
        int r = idx >> 3, seg = idx & 7;
        uint32_t off = (uint32_t)(r * 144 + seg * 16);
        const size_t go = (size_t)(m0 + r) * E_DIM + k0 + seg * 8;
        cp_async16(st + off, Ahi + go);
        cp_async16(st + A_TB + off, Alo + go);
    }
#pragma unroll
    for (int it = 0; it < 4; it++) {
        int idx = tid + it * 256;            // 0..1023
        int r = idx >> 3, seg = idx & 7;
        uint32_t off = (uint32_t)(r * 144 + seg * 16);
        const size_t go = (size_t)(n0 + r) * E_DIM + k0 + seg * 8;
        cp_async16(st + 2 * A_TB + off, Bhi + go);
        cp_async16(st + 2 * A_TB + B_TB + off, Blo + go);
    }
}

__device__ __forceinline__ void gemm_mainloop(
    const __nv_bfloat16* __restrict__ Ahi, const __nv_bfloat16* __restrict__ Alo,
    const __nv_bfloat16* __restrict__ Bthi, const __nv_bfloat16* __restrict__ Btlo,
    int m0, int n0, uint32_t sbase, int tid, int wm, int wn, int lane,
    float acc[4][8][4]) {

    load_chunk_async(Ahi, Alo, Bthi, Btlo, m0, n0, 0, sbase, tid);
    asm volatile("cp.async.commit_group;");

    for (int c = 0; c < NCHUNK; c++) {
        asm volatile("cp.async.wait_group 0;");
        __syncthreads();   // publishes chunk c; guards overwrite of buf (c+1)&1
        if (c + 1 < NCHUNK) {
            load_chunk_async(Ahi, Alo, Bthi, Btlo, m0, n0, (c + 1) << 6,
                             sbase + ((c + 1) & 1) * BUF_BYTES, tid);
            asm volatile("cp.async.commit_group;");
        }

        const uint32_t st = sbase + (c & 1) * BUF_BYTES;
        const uint32_t Ahi_s = st, Alo_s = st + A_TB;
        const uint32_t Bhi_s = st + 2 * A_TB, Blo_s = st + 2 * A_TB + B_TB;

#pragma unroll
        for (int ks = 0; ks < 4; ks++) {
            uint32_t ah[4][4], al[4][4];
#pragma unroll
            for (int mt = 0; mt < 4; mt++) {
                int row = wm * 64 + mt * 16 + (lane & 15);
                int kb = ks * 16 + ((lane >> 4) << 3);
                uint32_t off = (uint32_t)(row * 144 + kb * 2);
                ldmatrix_x4(ah[mt], Ahi_s + off);
                ldmatrix_x4(al[mt], Alo_s + off);
            }
#pragma unroll
            for (int np = 0; np < 4; np++) {
                uint32_t bh[4], bl[4];
                int row = wn * 64 + np * 16 + ((lane >> 4) << 3) + (lane & 7);
                int kb = ks * 16 + (((lane >> 3) & 1) << 3);
                uint32_t off = (uint32_t)(row * 144 + kb * 2);
                ldmatrix_x4(bh, Bhi_s + off);
                ldmatrix_x4(bl, Blo_s + off);
#pragma unroll
                for (int half = 0; half < 2; half++)
#pragma unroll
                    for (int mt = 0; mt < 4; mt++)
                        mma16816(acc[mt][2 * np + half], ah[mt], bh + 2 * half);
#pragma unroll
                for (int half = 0; half < 2; half++)
#pragma unroll
                    for (int mt = 0; mt < 4; mt++)
                        mma16816(acc[mt][2 * np + half], ah[mt], bl + 2 * half);
#pragma unroll
                for (int half = 0; half < 2; half++)
#pragma unroll
                    for (int mt = 0; mt < 4; mt++)
                        mma16816(acc[mt][2 * np + half], al[mt], bh + 2 * half);
            }
        }
    }
}

// Fused QKV projection: z = 0:Q(+RoPE+scale) 1:K(+RoPE) 2:V
__global__ __launch_bounds__(256)
void tgemm_qkv_kernel() {
    extern __shared__ __align__(1024) char dsm[];
    const uint32_t sbase = smem_u32(dsm);
    const int tid = threadIdx.x;
    const int wid = tid >> 5, lane = tid & 31;
    const int wm = wid & 3, wn = wid >> 2;
    const int g = lane >> 2, tg = lane & 3;
    const int m0 = blockIdx.y << 8, n0 = blockIdx.x << 7;
    const int z = blockIdx.z;

    const __nv_bfloat16* Bthi = g_wthi[z];
    const __nv_bfloat16* Btlo = g_wtlo[z];
    const float* bias = g_bias + (z << 10);
    __nv_bfloat16* Chi = (z == 0) ? g_qhi : (z == 1) ? g_khi : g_vhi;
    __nv_bfloat16* Clo = (z == 0) ? g_qlo : (z == 1) ? g_klo : g_vlo;

    float acc[4][8][4] = {};
    gemm_mainloop(g_xhi, g_xlo, Bthi, Btlo, m0, n0, sbase, tid, wm, wn, lane, acc);

    const int h = (n0 + wn * 64) >> 6;
#pragma unroll
    for (int mt = 0; mt < 4; mt++) {
#pragma unroll
        for (int h2 = 0; h2 < 2; h2++) {
            int m = m0 + wm * 64 + mt * 16 + g + h2 * 8;
            int bb = m >> 11, s = m & (S_LEN - 1);
            size_t rb = (((size_t)(bb * N_HEADS + h)) * S_LEN + s) << 6;
            float vals[8][2];
#pragma unroll
            for (int nt = 0; nt < 8; nt++) {
                int col = nt * 8 + tg * 2;
                float2 bv = *(const float2*)&bias[n0 + wn * 64 + col];
                vals[nt][0] = acc[mt][nt][h2 * 2 + 0] + bv.x;
                vals[nt][1] = acc[mt][nt][h2 * 2 + 1] + bv.y;
            }
            if (z < 2) {
#pragma unroll
                for (int nt = 0; nt < 4; nt++) {
#pragma unroll
                    for (int jj = 0; jj < 2; jj++) {
                        int d = nt * 8 + tg * 2 + jj;
                        float cth = g_cos[(s << 5) + d];
                        float sth = g_sin[(s << 5) + d];
                        float lo = vals[nt][jj], hi = vals[nt + 4][jj];
                        vals[nt][jj]     = fmaf(lo, cth, -hi * sth);
                        vals[nt + 4][jj] = fmaf(hi, cth,  lo * sth);
                    }
                }
            }
            if (z == 0) {
#pragma unroll
                for (int nt = 0; nt < 8; nt++) {
                    vals[nt][0] *= SCALE_Q;
                    vals[nt][1] *= SCALE_Q;
                }
            }
#pragma unroll
            for (int nt = 0; nt < 8; nt++) {
                uint32_t hv, lv;
                split2(vals[nt][0], vals[nt][1], hv, lv);
                *(uint32_t*)(Chi + rb + nt * 8 + tg * 2) = hv;
                *(uint32_t*)(Clo + rb + nt * 8 + tg * 2) = lv;
            }
        }
    }
}

// Output projection
__global__ __launch_bounds__(256)
void tgemm_out_kernel(const float* __restrict__ bias, float* __restrict__ C) {
    extern __shared__ __align__(1024) char dsm[];
    const uint32_t sbase = smem_u32(dsm);
    const int tid = threadIdx.x;
    const int wid = tid >> 5, lane = tid & 31;
    const int wm = wid & 3, wn = wid >> 2;
    const int g = lane >> 2, tg = lane & 3;
    const int m0 = blockIdx.y << 8, n0 = blockIdx.x << 7;

    float acc[4][8][4] = {};
    gemm_mainloop(g_chi, g_clo, g_wthi[3], g_wtlo[3], m0, n0, sbase, tid, wm, wn, lane, acc);

#pragma unroll
    for (int mt = 0; mt < 4; mt++) {
#pragma unroll
        for (int h2 = 0; h2 < 2; h2++) {
            int m = m0 + wm * 64 + mt * 16 + g + h2 * 8;
            float* dst = &C[(size_t)m * E_DIM + n0 + wn * 64];
#pragma unroll
            for (int nt = 0; nt < 8; nt++) {
                int col = nt * 8 + tg * 2;
                float2 bv = *(const float2*)&bias[n0 + wn * 64 + col];
                *(float2*)&dst[col] = make_float2(acc[mt][nt][h2 * 2 + 0] + bv.x,
                                                  acc[mt][nt][h2 * 2 + 1] + bv.y);
            }
        }
    }
}

// ---------------------------------------------------------------------------
// Tensorized flash attention. Q-tile 128, KV-tile 128, 8 warps.
// ---------------------------------------------------------------------------
#define ATT_Q    0
#define ATT_QL   18432
#define ATT_BUF0 36864
#define ATT_BUFSZ 74240
#define ATT_SMEM (36864 + 2 * ATT_BUFSZ)

__device__ __forceinline__ void attn_issue_kv(
    const __nv_bfloat16* khi, const __nv_bfloat16* klo,
    const __nv_bfloat16* vhi, const __nv_bfloat16* vlo,
    const int* mask, int mask_off, uint32_t sb, int t, int tid) {
    uint32_t bufb = sb + ATT_BUF0 + (t & 1) * ATT_BUFSZ;
    int k0 = t << 7;
    const __nv_bfloat16* srcs[4] = {khi, klo, vhi, vlo};
#pragma unroll
    for (int i = 0; i < 16; i++) {
        int idx = tid + i * 256;
        int arr = idx >> 10;
        int r = (idx >> 3) & 127, seg = idx & 7;
        cp_async16(bufb + arr * 18432 + (uint32_t)(r * 144 + seg * 16),
                   srcs[arr] + (size_t)(k0 + r) * HD + seg * 8);
    }
    if (tid < 32)
        cp_async16(bufb + 73728 + tid * 16, mask + mask_off + k0 + tid * 4);
}

__global__ __launch_bounds__(256)
void attn_kernel(const int* __restrict__ mask) {
    extern __shared__ __align__(1024) char sm_[];
    const uint32_t sb = smem_u32(sm_);
    const int tid = threadIdx.x, w = tid >> 5, lane = tid & 31;
    const int g = lane >> 2, tg = lane & 3;
    const int qt = gridDim.x - 1 - blockIdx.x;
    const int bh = blockIdx.y, bb = bh >> 4, hh = bh & 15;
    const int q0 = qt << 7;
    const size_t base = (size_t)bh * S_LEN * HD;

    {
        const __nv_bfloat16* s0 = g_qhi + base + (size_t)q0 * HD;
        const __nv_bfloat16* s1 = g_qlo + base + (size_t)q0 * HD;
#pragma unroll
        for (int i = 0; i < 8; i++) {
            int idx = tid + i * 256;
            int arr = idx >> 10;
            int r = (idx >> 3) & 127, seg = idx & 7;
            uint4 v = *(const uint4*)((arr ? s1 : s0) + (size_t)r * HD + seg * 8);
            *(uint4*)(sm_ + (arr ? ATT_QL : ATT_Q) + r * 144 + seg * 16) = v;
        }
    }

    const int ntile = qt + 1;
    attn_issue_kv(g_khi + base, g_klo + base, g_vhi + base, g_vlo + base,
                  mask, bb * S_LEN, sb, 0, tid);
    asm volatile("cp.async.commit_group;");
    __syncthreads();

    uint32_t qfh[4][4], qfl[4][4];
    {
        int i = lane & 15;
        int prow = (i < 8) ? (w * 8 + i) : (64 + w * 8 + (i - 8));
        int kb = ((lane >> 4) << 3);
#pragma unroll
        for (int ks = 0; ks < 4; ks++) {
            uint32_t off = (uint32_t)(prow * 144 + (ks * 16 + kb) * 2);
            ldmatrix_x4(qfh[ks], sb + ATT_Q + off);
            ldmatrix_x4(qfl[ks], sb + ATT_QL + off);
        }
    }
    const int row0 = q0 + w * 8 + g;
    const int row1 = q0 + 64 + w * 8 + g;

    float oacc[8][4] = {};
    float l0 = 0.f, l1 = 0.f, mo0 = -1e30f, mo1 = -1e30f;

    for (int t = 0; t < ntile; t++) {
        asm volatile("cp.async.wait_group 0;");
        __syncthreads();
        if (t + 1 < ntile) {
            attn_issue_kv(g_khi + base, g_klo + base, g_vhi + base, g_vlo + base,
                          mask, bb * S_LEN, sb, t + 1, tid);
            asm volatile("cp.async.commit_group;");
        }
        const uint32_t bufb = sb + ATT_BUF0 + (t & 1) * ATT_BUFSZ;
        const int k0 = t << 7;

        float sc[16][4] = {};
#pragma unroll
        for (int ks = 0; ks < 4; ks++) {
#pragma unroll
            for (int ntp = 0; ntp < 8; ntp++) {
                uint32_t kh[4], kl[4];
                int row = ntp * 16 + ((lane >> 4) << 3) + (lane & 7);
                int kb = ks * 16 + (((lane >> 3) & 1) << 3);
                uint32_t off = (uint32_t)(row * 144 + kb * 2);
                ldmatrix_x4(kh, bufb + off);
                ldmatrix_x4(kl, bufb + 18432 + off);
#pragma unroll
                for (int hf = 0; hf < 2; hf++)
                    mma16816(sc[2 * ntp + hf], qfh[ks], kh + 2 * hf);
#pragma unroll
                for (int hf = 0; hf < 2; hf++)
                    mma16816(sc[2 * ntp + hf], qfh[ks], kl + 2 * hf);
#pragma unroll
                for (int hf = 0; hf < 2; hf++)
                    mma16816(sc[2 * ntp + hf], qfl[ks], kh + 2 * hf);
            }
        }

        const int* Ms = (const int*)(sm_ + ATT_BUF0 + (t & 1) * ATT_BUFSZ + 73728);
        uint32_t pb[4];
        pb[0] = __ballot_sync(0xffffffffu, Ms[lane] != 0);
        pb[1] = __ballot_sync(0xffffffffu, Ms[lane + 32] != 0);
        pb[2] = __ballot_sync(0xffffffffu, Ms[lane + 64] != 0);
        pb[3] = __ballot_sync(0xffffffffu, Ms[lane + 96] != 0);
        if ((pb[0] & pb[1] & pb[2] & pb[3]) != 0xffffffffu) {
#pragma unroll
            for (int nt = 0; nt < 16; nt++)
#pragma unroll
                for (int j = 0; j < 2; j++) {
                    int cl = nt * 8 + tg * 2 + j;
                    if (!((pb[cl >> 5] >> (cl & 31)) & 1)) {
                        sc[nt][j] = -1e30f;
                        sc[nt][2 + j] = -1e30f;
                    }
                }
        }
        if (k0 + 127 > row0) {
#pragma unroll
            for (int nt = 0; nt < 16; nt++)
#pragma unroll
                for (int j = 0; j < 2; j++) {
                    int cg = k0 + nt * 8 + tg * 2 + j;
                    if (cg > row0) sc[nt][j] = -1e30f;
                    if (cg > row1) sc[nt][2 + j] = -1e30f;
                }
        }

        float mx0 = -1e30f, mx1 = -1e30f;
#pragma unroll
        for (int nt = 0; nt < 16; nt++) {
            mx0 = fmaxf(mx0, fmaxf(sc[nt][0], sc[nt][1]));
            mx1 = fmaxf(mx1, fmaxf(sc[nt][2], sc[nt][3]));
        }
        mx0 = fmaxf(mx0, __shfl_xor_sync(0xffffffffu, mx0, 1));
        mx0 = fmaxf(mx0, __shfl_xor_sync(0xffffffffu, mx0, 2));
        mx1 = fmaxf(mx1, __shfl_xor_sync(0xffffffffu, mx1, 1));
        mx1 = fmaxf(mx1, __shfl_xor_sync(0xffffffffu, mx1, 2));
        float mn0 = fmaxf(mo0, mx0), mn1 = fmaxf(mo1, mx1);
        float al0 = ex2(mo0 - mn0), al1 = ex2(mo1 - mn1);
        float rs0 = 0.f, rs1 = 0.f;
#pragma unroll
        for (int nt = 0; nt < 16; nt++) {
            sc[nt][0] = ex2(sc[nt][0] - mn0);
            sc[nt][1] = ex2(sc[nt][1] - mn0);
            sc[nt][2] = ex2(sc[nt][2] - mn1);
            sc[nt][3] = ex2(sc[nt][3] - mn1);
            rs0 += sc[nt][0] + sc[nt][1];
            rs1 += sc[nt][2] + sc[nt][3];
        }
        rs0 += __shfl_xor_sync(0xffffffffu, rs0, 1);
        rs0 += __shfl_xor_sync(0xffffffffu, rs0, 2);
        rs1 += __shfl_xor_sync(0xffffffffu, rs1, 1);
        rs1 += __shfl_xor_sync(0xffffffffu, rs1, 2);
        l0 = l0 * al0 + rs0;
        l1 = l1 * al1 + rs1;
        mo0 = mn0; mo1 = mn1;
#pragma unroll
        for (int nt = 0; nt < 8; nt++) {
            oacc[nt][0] *= al0; oacc[nt][1] *= al0;
            oacc[nt][2] *= al1; oacc[nt][3] *= al1;
        }

#pragma unroll
        for (int ks = 0; ks < 8; ks++) {
            uint32_t pa[4], pl[4];
            split2(sc[2 * ks][0], sc[2 * ks][1], pa[0], pl[0]);
            split2(sc[2 * ks][2], sc[2 * ks][3], pa[1], pl[1]);
            split2(sc[2 * ks + 1][0], sc[2 * ks + 1][1], pa[2], pl[2]);
            split2(sc[2 * ks + 1][2], sc[2 * ks + 1][3], pa[3], pl[3]);
#pragma unroll
            for (int dtp = 0; dtp < 4; dtp++) {
                uint32_t vh[4], vl[4];
                int rkv = ks * 16 + ((lane >> 3) & 1) * 8 + (lane & 7);
                int cd = dtp * 16 + (lane >> 4) * 8;
                uint32_t off = (uint32_t)(rkv * 144 + cd * 2);
                ldmatrix_x4_trans(vh, bufb + 36864 + off);
                ldmatrix_x4_trans(vl, bufb + 55296 + off);
#pragma unroll
                for (int hf = 0; hf < 2; hf++)
                    mma16816(oacc[2 * dtp + hf], pa, vh + 2 * hf);
#pragma unroll
                for (int hf = 0; hf < 2; hf++)
                    mma16816(oacc[2 * dtp + hf], pa, vl + 2 * hf);
#pragma unroll
                for (int hf = 0; hf < 2; hf++)
                    mma16816(oacc[2 * dtp + hf], pl, vh + 2 * hf);
            }
        }
    }

    float inv0 = 1.0f / l0, inv1 = 1.0f / l1;
    __nv_bfloat16* dh0 = g_chi + ((size_t)(bb * S_LEN + row0)) * E_DIM + hh * 64;
    __nv_bfloat16* dl0 = g_clo + ((size_t)(bb * S_LEN + row0)) * E_DIM + hh * 64;
    __nv_bfloat16* dh1 = g_chi + ((size_t)(bb * S_LEN + row1)) * E_DIM + hh * 64;
    __nv_bfloat16* dl1 = g_clo + ((size_t)(bb * S_LEN + row1)) * E_DIM + hh * 64;
#pragma unroll
    for (int nt = 0; nt < 8; nt++) {
        int d = nt * 8 + tg * 2;
        uint32_t hv, lv;
        split2(oacc[nt][0] * inv0, oacc[nt][1] * inv0, hv, lv);
        *(uint32_t*)(dh0 + d) = hv;
        *(uint32_t*)(dl0 + d) = lv;
        split2(oacc[nt][2] * inv1, oacc[nt][3] * inv1, hv, lv);
        *(uint32_t*)(dh1 + d) = hv;
        *(uint32_t*)(dl1 + d) = lv;
    }
}

// ---------------------------------------------------------------------------
extern "C" void kernel_launch(void* const* d_in, const int* in_sizes, int n_in,
                              void* d_out, int out_size) {
    const float* x    = (const float*)d_in[0];
    const int*   mask = (const int*)d_in[1];
    const float* Wq   = (const float*)d_in[2];
    const float* bq   = (const float*)d_in[3];
    const float* Wk   = (const float*)d_in[4];
    const float* bk   = (const float*)d_in[5];
    const float* Wv   = (const float*)d_in[6];
    const float* bv   = (const float*)d_in[7];
    const float* Wo   = (const float*)d_in[8];
    const float* bo   = (const float*)d_in[9];
    float* out = (float*)d_out;

    __nv_bfloat16 *pxhi, *pxlo;
    cudaGetSymbolAddress((void**)&pxhi, g_xhi);
    cudaGetSymbolAddress((void**)&pxlo, g_xlo);

    // weight transpose first (independent; warms L2 before the QKV GEMM)
    cvt_transpose4_kernel<<<dim3(32, 32, 4), 256>>>(Wq, Wk, Wv, Wo);

    rope_table_kernel<<<(S_LEN * 32 + 255) / 256, 256>>>(bq, bk, bv);

    const int n4 = M_ROWS * E_DIM / 4;
    cvt_split_kernel<<<(n4 + 255) / 256, 256>>>(
        (const float4*)x, (__nv_bfloat162*)pxhi, (__nv_bfloat162*)pxlo, n4);

    cudaFuncSetAttribute(tgemm_qkv_kernel, cudaFuncAttributeMaxDynamicSharedMemorySize, GSMEM);
    cudaFuncSetAttribute(tgemm_out_kernel, cudaFuncAttributeMaxDynamicSharedMemorySize, GSMEM);
    cudaFuncSetAttribute(attn_kernel, cudaFuncAttributeMaxDynamicSharedMemorySize, ATT_SMEM);

    tgemm_qkv_kernel<<<dim3(E_DIM / 128, M_ROWS / 256, 3), 256, GSMEM>>>();

    attn_kernel<<<dim3(S_LEN / 128, BATCH * N_HEADS), 256, ATT_SMEM>>>(mask);

    tgemm_out_kernel<<<dim3(E_DIM / 128, M_ROWS / 256), 256, GSMEM>>>(bo, out);
}

// round 12
// speedup vs baseline: 2.1762x; 1.2237x over previous
#include <cuda_runtime.h>
#include <cuda_bf16.h>
#include <cuda_fp16.h>
#include <math.h>
#include <stdint.h>

#define S_LEN 2048
#define E_DIM 1024
#define N_HEADS 16
#define HD 64
#define BATCH 2
#define M_ROWS 4096
#define SCALE_Q 0.18033688011112042f   // 0.125 * log2(e)

// ---------------- scratch ---------------------------------------------------
__device__ __align__(256) float g_cos[S_LEN * 32];
__device__ __align__(256) float g_sin[S_LEN * 32];
__device__ __align__(256) float g_bias[3 * E_DIM];
__device__ __align__(256) __half g_xh[(size_t)M_ROWS * E_DIM];          // x, fp16
__device__ __align__(256) __half g_ch[(size_t)M_ROWS * E_DIM];          // ctx, fp16
__device__ __align__(256) __half g_wth[4][(size_t)E_DIM * E_DIM];       // W^T hi fp16
__device__ __align__(256) __half g_wtl[4][(size_t)E_DIM * E_DIM];       // W^T lo fp16
__device__ __align__(256) __nv_bfloat16 g_qhi[(size_t)M_ROWS * E_DIM];
__device__ __align__(256) __nv_bfloat16 g_qlo[(size_t)M_ROWS * E_DIM];
__device__ __align__(256) __nv_bfloat16 g_khi[(size_t)M_ROWS * E_DIM];
__device__ __align__(256) __nv_bfloat16 g_klo[(size_t)M_ROWS * E_DIM];
__device__ __align__(256) __nv_bfloat16 g_vhi[(size_t)M_ROWS * E_DIM];
__device__ __align__(256) __nv_bfloat16 g_vlo[(size_t)M_ROWS * E_DIM];

// ---------------- helpers ---------------------------------------------------
__device__ __forceinline__ uint32_t smem_u32(const void* p) {
    uint32_t a;
    asm("{ .reg .u64 t; cvta.to.shared.u64 t, %1; cvt.u32.u64 %0, t; }"
        : "=r"(a) : "l"(p));
    return a;
}
__device__ __forceinline__ void ldmatrix_x4(uint32_t* r, uint32_t addr) {
    asm volatile("ldmatrix.sync.aligned.m8n8.x4.shared.b16 {%0,%1,%2,%3}, [%4];"
                 : "=r"(r[0]), "=r"(r[1]), "=r"(r[2]), "=r"(r[3]) : "r"(addr));
}
__device__ __forceinline__ void ldmatrix_x4_trans(uint32_t* r, uint32_t addr) {
    asm volatile("ldmatrix.sync.aligned.m8n8.x4.trans.shared.b16 {%0,%1,%2,%3}, [%4];"
                 : "=r"(r[0]), "=r"(r[1]), "=r"(r[2]), "=r"(r[3]) : "r"(addr));
}
__device__ __forceinline__ void mma16816(float* c, const uint32_t* a, const uint32_t* b) {
    asm("mma.sync.aligned.m16n8k16.row.col.f32.bf16.bf16.f32 "
        "{%0,%1,%2,%3}, {%4,%5,%6,%7}, {%8,%9}, {%0,%1,%2,%3};"
        : "+f"(c[0]), "+f"(c[1]), "+f"(c[2]), "+f"(c[3])
        : "r"(a[0]), "r"(a[1]), "r"(a[2]), "r"(a[3]), "r"(b[0]), "r"(b[1]));
}
__device__ __forceinline__ void mma16816h(float* c, const uint32_t* a, const uint32_t* b) {
    asm("mma.sync.aligned.m16n8k16.row.col.f32.f16.f16.f32 "
        "{%0,%1,%2,%3}, {%4,%5,%6,%7}, {%8,%9}, {%0,%1,%2,%3};"
        : "+f"(c[0]), "+f"(c[1]), "+f"(c[2]), "+f"(c[3])
        : "r"(a[0]), "r"(a[1]), "r"(a[2]), "r"(a[3]), "r"(b[0]), "r"(b[1]));
}
__device__ __forceinline__ void cp_async16(uint32_t dst, const void* src) {
    asm volatile("cp.async.cg.shared.global [%0], [%1], 16;" :: "r"(dst), "l"(src));
}
__device__ __forceinline__ float ex2(float x) {
    float y;
    asm("ex2.approx.f32 %0, %1;" : "=f"(y) : "f"(x));
    return y;
}
__device__ __forceinline__ void split2(float x, float y, uint32_t& h, uint32_t& l) {
    __nv_bfloat162 hb = __floats2bfloat162_rn(x, y);
    float2 hf = __bfloat1622float2(hb);
    __nv_bfloat162 lb = __floats2bfloat162_rn(x - hf.x, y - hf.y);
    h = *(uint32_t*)&hb;
    l = *(uint32_t*)&lb;
}

// ---------------------------------------------------------------------------
__global__ void rope_table_kernel(const float* __restrict__ bq,
                                  const float* __restrict__ bk,
                                  const float* __restrict__ bv) {
    int i = blockIdx.x * blockDim.x + threadIdx.x;
    if (i < 3 * E_DIM) {
        const float* b = (i < E_DIM) ? bq : (i < 2 * E_DIM) ? bk : bv;
        g_bias[i] = b[i & (E_DIM - 1)];
    }
    if (i >= S_LEN * 32) return;
    int s = i >> 5, j = i & 31;
    float inv = (float)pow(10000.0, -(double)j / 32.0);
    float th = (float)s * inv;
    g_cos[i] = cosf(th);
    g_sin[i] = sinf(th);
}

// x: f32 -> fp16 single
__global__ void cvt_half_kernel(const float4* __restrict__ src, int n4) {
    int i = blockIdx.x * blockDim.x + threadIdx.x;
    if (i >= n4) return;
    float4 v = src[i];
    __half2* dst = (__half2*)g_xh;
    dst[2 * i]     = __floats2half2_rn(v.x, v.y);
    dst[2 * i + 1] = __floats2half2_rn(v.z, v.w);
}

// transpose + fp16 hi/lo split for all 4 weights
__global__ void cvt_transpose4_kernel(const float* __restrict__ W0,
                                      const float* __restrict__ W1,
                                      const float* __restrict__ W2,
                                      const float* __restrict__ W3) {
    __shared__ float t[32][33];
    const float* Ws[4] = {W0, W1, W2, W3};
    const float* W = Ws[blockIdx.z];
    __half* th = g_wth[blockIdx.z];
    __half* tl = g_wtl[blockIdx.z];
    int bx = blockIdx.x, by = blockIdx.y;
    int tid = threadIdx.x;
#pragma unroll
    for (int it = 0; it < 4; it++) {
        int idx = tid + it * 256;
        int r = idx >> 5, c = idx & 31;
        t[r][c] = W[(size_t)(by * 32 + r) * E_DIM + bx * 32 + c];
    }
    __syncthreads();
#pragma unroll
    for (int it = 0; it < 4; it++) {
        int idx = tid + it * 256;
        int r = idx >> 5, c = idx & 31;
        float x = t[c][r];
        __half h = __float2half_rn(x);
        size_t o = (size_t)(bx * 32 + r) * E_DIM + by * 32 + c;
        th[o] = h;
        tl[o] = __float2half_rn(x - __half2float(h));
    }
}

// ---------------------------------------------------------------------------
// 2-term fp16 GEMM: C = A * (Bhi + Blo),  A single fp16, B split fp16.
// CTA tile 256x128, BK=64, 8 warps (4x2), warp tile 64x64.
// ---------------------------------------------------------------------------
#define A_TB 36864                     // 256 rows * 144 B
#define B_TB 18432                     // 128 rows * 144 B
#define BUF_BYTES (A_TB + 2 * B_TB)    // 73728
#define GSMEM (2 * BUF_BYTES)          // 147456
#define NCHUNK 16

__device__ __forceinline__ void load_chunk_async(
    const __half* __restrict__ A,
    const __half* __restrict__ Bhi, const __half* __restrict__ Blo,
    int m0, int n0, int k0, uint32_t st, int tid) {
#pragma unroll
    for (int it = 0; it < 8; it++) {
        int idx = tid + it * 256;            // 0..2047
        int r = idx >> 3, seg = idx & 7;
        cp_async16(st + (uint32_t)(r * 144 + seg * 16),
                   A + (size_t)(m0 + r) * E_DIM + k0 + seg * 8);
    }
#pragma unroll
    for (int it = 0; it < 4; it++) {
        int idx = tid + it * 256;            // 0..1023
        int r = idx >> 3, seg = idx & 7;
        uint32_t off = (uint32_t)(r * 144 + seg * 16);
        const size_t go = (size_t)(n0 + r) * E_DIM + k0 + seg * 8;
        cp_async16(st + A_TB + off, Bhi + go);
        cp_async16(st + A_TB + B_TB + off, Blo + go);
    }
}

__device__ __forceinline__ void gemm_mainloop(
    const __half* __restrict__ A,
    const __half* __restrict__ Bhi, const __half* __restrict__ Blo,
    int m0, int n0, uint32_t sbase, int tid, int wm, int wn, int lane,
    float acc[4][8][4]) {

    load_chunk_async(A, Bhi, Blo, m0, n0, 0, sbase, tid);
    asm volatile("cp.async.commit_group;");

    for (int c = 0; c < NCHUNK; c++) {
        asm volatile("cp.async.wait_group 0;");
        __syncthreads();   // publishes chunk c; guards overwrite of buf (c+1)&1
        if (c + 1 < NCHUNK) {
            load_chunk_async(A, Bhi, Blo, m0, n0, (c + 1) << 6,
                             sbase + ((c + 1) & 1) * BUF_BYTES, tid);
            asm volatile("cp.async.commit_group;");
        }

        const uint32_t st = sbase + (c & 1) * BUF_BYTES;
        const uint32_t A_s = st;
        const uint32_t Bhi_s = st + A_TB, Blo_s = st + A_TB + B_TB;

#pragma unroll
        for (int ks = 0; ks < 4; ks++) {
            uint32_t af[4][4];
#pragma unroll
            for (int mt = 0; mt < 4; mt++) {
                int row = wm * 64 + mt * 16 + (lane & 15);
                int kb = ks * 16 + ((lane >> 4) << 3);
                ldmatrix_x4(af[mt], A_s + (uint32_t)(row * 144 + kb * 2));
            }
#pragma unroll
            for (int np = 0; np < 4; np++) {
                uint32_t bh[4], bl[4];
                int row = wn * 64 + np * 16 + ((lane >> 4) << 3) + (lane & 7);
                int kb = ks * 16 + (((lane >> 3) & 1) << 3);
                uint32_t off = (uint32_t)(row * 144 + kb * 2);
                ldmatrix_x4(bh, Bhi_s + off);
                ldmatrix_x4(bl, Blo_s + off);
#pragma unroll
                for (int half = 0; half < 2; half++)
#pragma unroll
                    for (int mt = 0; mt < 4; mt++)
                        mma16816h(acc[mt][2 * np + half], af[mt], bh + 2 * half);
#pragma unroll
                for (int half = 0; half < 2; half++)
#pragma unroll
                    for (int mt = 0; mt < 4; mt++)
                        mma16816h(acc[mt][2 * np + half], af[mt], bl + 2 * half);
            }
        }
    }
}

// Fused QKV projection: z = 0:Q(+RoPE+scale) 1:K(+RoPE) 2:V
__global__ __launch_bounds__(256)
void tgemm_qkv_kernel() {
    extern __shared__ __align__(1024) char dsm[];
    const uint32_t sbase = smem_u32(dsm);
    const int tid = threadIdx.x;
    const int wid = tid >> 5, lane = tid & 31;
    const int wm = wid & 3, wn = wid >> 2;
    const int g = lane >> 2, tg = lane & 3;
    const int m0 = blockIdx.y << 8, n0 = blockIdx.x << 7;
    const int z = blockIdx.z;

    const float* bias = g_bias + (z << 10);
    __nv_bfloat16* Chi = (z == 0) ? g_qhi : (z == 1) ? g_khi : g_vhi;
    __nv_bfloat16* Clo = (z == 0) ? g_qlo : (z == 1) ? g_klo : g_vlo;

    float acc[4][8][4] = {};
    gemm_mainloop(g_xh, g_wth[z], g_wtl[z], m0, n0, sbase, tid, wm, wn, lane, acc);

    const int h = (n0 + wn * 64) >> 6;
#pragma unroll
    for (int mt = 0; mt < 4; mt++) {
#pragma unroll
        for (int h2 = 0; h2 < 2; h2++) {
            int m = m0 + wm * 64 + mt * 16 + g + h2 * 8;
            int bb = m >> 11, s = m & (S_LEN - 1);
            size_t rb = (((size_t)(bb * N_HEADS + h)) * S_LEN + s) << 6;
            float vals[8][2];
#pragma unroll
            for (int nt = 0; nt < 8; nt++) {
                int col = nt * 8 + tg * 2;
                float2 bv = *(const float2*)&bias[n0 + wn * 64 + col];
                vals[nt][0] = acc[mt][nt][h2 * 2 + 0] + bv.x;
                vals[nt][1] = acc[mt][nt][h2 * 2 + 1] + bv.y;
            }
            if (z < 2) {
#pragma unroll
                for (int nt = 0; nt < 4; nt++) {
#pragma unroll
                    for (int jj = 0; jj < 2; jj++) {
                        int d = nt * 8 + tg * 2 + jj;
                        float cth = g_cos[(s << 5) + d];
                        float sth = g_sin[(s << 5) + d];
                        float lo = vals[nt][jj], hi = vals[nt + 4][jj];
                        vals[nt][jj]     = fmaf(lo, cth, -hi * sth);
                        vals[nt + 4][jj] = fmaf(hi, cth,  lo * sth);
                    }
                }
            }
            if (z == 0) {
#pragma unroll
                for (int nt = 0; nt < 8; nt++) {
                    vals[nt][0] *= SCALE_Q;
                    vals[nt][1] *= SCALE_Q;
                }
            }
#pragma unroll
            for (int nt = 0; nt < 8; nt++) {
                uint32_t hv, lv;
                split2(vals[nt][0], vals[nt][1], hv, lv);
                *(uint32_t*)(Chi + rb + nt * 8 + tg * 2) = hv;
                *(uint32_t*)(Clo + rb + nt * 8 + tg * 2) = lv;
            }
        }
    }
}

// Output projection: out = ctx(fp16) @ (Wohi + Wolo) + bo
__global__ __launch_bounds__(256)
void tgemm_out_kernel(const float* __restrict__ bias, float* __restrict__ C) {
    extern __shared__ __align__(1024) char dsm[];
    const uint32_t sbase = smem_u32(dsm);
    const int tid = threadIdx.x;
    const int wid = tid >> 5, lane = tid & 31;
    const int wm = wid & 3, wn = wid >> 2;
    const int g = lane >> 2, tg = lane & 3;
    const int m0 = blockIdx.y << 8, n0 = blockIdx.x << 7;

    float acc[4][8][4] = {};
    gemm_mainloop(g_ch, g_wth[3], g_wtl[3], m0, n0, sbase, tid, wm, wn, lane, acc);

#pragma unroll
    for (int mt = 0; mt < 4; mt++) {
#pragma unroll
        for (int h2 = 0; h2 < 2; h2++) {
            int m = m0 + wm * 64 + mt * 16 + g + h2 * 8;
            float* dst = &C[(size_t)m * E_DIM + n0 + wn * 64];
#pragma unroll
            for (int nt = 0; nt < 8; nt++) {
                int col = nt * 8 + tg * 2;
                float2 bv = *(const float2*)&bias[n0 + wn * 64 + col];
                *(float2*)&dst[col] = make_float2(acc[mt][nt][h2 * 2 + 0] + bv.x,
                                                  acc[mt][nt][h2 * 2 + 1] + bv.y);
            }
        }
    }
}

// ---------------------------------------------------------------------------
// Tensorized flash attention (3-term bf16, unchanged except fp16 ctx output).
// ---------------------------------------------------------------------------
#define ATT_Q    0
#define ATT_QL   18432
#define ATT_BUF0 36864
#define ATT_BUFSZ 74240
#define ATT_SMEM (36864 + 2 * ATT_BUFSZ)

__device__ __forceinline__ void attn_issue_kv(
    const __nv_bfloat16* khi, const __nv_bfloat16* klo,
    const __nv_bfloat16* vhi, const __nv_bfloat16* vlo,
    const int* mask, int mask_off, uint32_t sb, int t, int tid) {
    uint32_t bufb = sb + ATT_BUF0 + (t & 1) * ATT_BUFSZ;
    int k0 = t << 7;
    const __nv_bfloat16* srcs[4] = {khi, klo, vhi, vlo};
#pragma unroll
    for (int i = 0; i < 16; i++) {
        int idx = tid + i * 256;
        int arr = idx >> 10;
        int r = (idx >> 3) & 127, seg = idx & 7;
        cp_async16(bufb + arr * 18432 + (uint32_t)(r * 144 + seg * 16),
                   srcs[arr] + (size_t)(k0 + r) * HD + seg * 8);
    }
    if (tid < 32)
        cp_async16(bufb + 73728 + tid * 16, mask + mask_off + k0 + tid * 4);
}

__global__ __launch_bounds__(256)
void attn_kernel(const int* __restrict__ mask) {
    extern __shared__ __align__(1024) char sm_[];
    const uint32_t sb = smem_u32(sm_);
    const int tid = threadIdx.x, w = tid >> 5, lane = tid & 31;
    const int g = lane >> 2, tg = lane & 3;
    const int qt = gridDim.x - 1 - blockIdx.x;
    const int bh = blockIdx.y, bb = bh >> 4, hh = bh & 15;
    const int q0 = qt << 7;
    const size_t base = (size_t)bh * S_LEN * HD;

    {
        const __nv_bfloat16* s0 = g_qhi + base + (size_t)q0 * HD;
        const __nv_bfloat16* s1 = g_qlo + base + (size_t)q0 * HD;
#pragma unroll
        for (int i = 0; i < 8; i++) {
            int idx = tid + i * 256;
            int arr = idx >> 10;
            int r = (idx >> 3) & 127, seg = idx & 7;
            uint4 v = *(const uint4*)((arr ? s1 : s0) + (size_t)r * HD + seg * 8);
            *(uint4*)(sm_ + (arr ? ATT_QL : ATT_Q) + r * 144 + seg * 16) = v;
        }
    }

    const int ntile = qt + 1;
    attn_issue_kv(g_khi + base, g_klo + base, g_vhi + base, g_vlo + base,
                  mask, bb * S_LEN, sb, 0, tid);
    asm volatile("cp.async.commit_group;");
    __syncthreads();

    uint32_t qfh[4][4], qfl[4][4];
    {
        int i = lane & 15;
        int prow = (i < 8) ? (w * 8 + i) : (64 + w * 8 + (i - 8));
        int kb = ((lane >> 4) << 3);
#pragma unroll
        for (int ks = 0; ks < 4; ks++) {
            uint32_t off = (uint32_t)(prow * 144 + (ks * 16 + kb) * 2);
            ldmatrix_x4(qfh[ks], sb + ATT_Q + off);
            ldmatrix_x4(qfl[ks], sb + ATT_QL + off);
        }
    }
    const int row0 = q0 + w * 8 + g;
    const int row1 = q0 + 64 + w * 8 + g;

    float oacc[8][4] = {};
    float l0 = 0.f, l1 = 0.f, mo0 = -1e30f, mo1 = -1e30f;

    for (int t = 0; t < ntile; t++) {
        asm volatile("cp.async.wait_group 0;");
        __syncthreads();
        if (t + 1 < ntile) {
            attn_issue_kv(g_khi + base, g_klo + base, g_vhi + base, g_vlo + base,
                          mask, bb * S_LEN, sb, t + 1, tid);
            asm volatile("cp.async.commit_group;");
        }
        const uint32_t bufb = sb + ATT_BUF0 + (t & 1) * ATT_BUFSZ;
        const int k0 = t << 7;

        float sc[16][4] = {};
#pragma unroll
        for (int ks = 0; ks < 4; ks++) {
#pragma unroll
            for (int ntp = 0; ntp < 8; ntp++) {
                uint32_t kh[4], kl[4];
                int row = ntp * 16 + ((lane >> 4) << 3) + (lane & 7);
                int kb = ks * 16 + (((lane >> 3) & 1) << 3);
                uint32_t off = (uint32_t)(row * 144 + kb * 2);
                ldmatrix_x4(kh, bufb + off);
                ldmatrix_x4(kl, bufb + 18432 + off);
#pragma unroll
                for (int hf = 0; hf < 2; hf++)
                    mma16816(sc[2 * ntp + hf], qfh[ks], kh + 2 * hf);
#pragma unroll
                for (int hf = 0; hf < 2; hf++)
                    mma16816(sc[2 * ntp + hf], qfh[ks], kl + 2 * hf);
#pragma unroll
                for (int hf = 0; hf < 2; hf++)
                    mma16816(sc[2 * ntp + hf], qfl[ks], kh + 2 * hf);
            }
        }

        const int* Ms = (const int*)(sm_ + ATT_BUF0 + (t & 1) * ATT_BUFSZ + 73728);
        uint32_t pb[4];
        pb[0] = __ballot_sync(0xffffffffu, Ms[lane] != 0);
        pb[1] = __ballot_sync(0xffffffffu, Ms[lane + 32] != 0);
        pb[2] = __ballot_sync(0xffffffffu, Ms[lane + 64] != 0);
        pb[3] = __ballot_sync(0xffffffffu, Ms[lane + 96] != 0);
        if ((pb[0] & pb[1] & pb[2] & pb[3]) != 0xffffffffu) {
#pragma unroll
            for (int nt = 0; nt < 16; nt++)
#pragma unroll
                for (int j = 0; j < 2; j++) {
                    int cl = nt * 8 + tg * 2 + j;
                    if (!((pb[cl >> 5] >> (cl & 31)) & 1)) {
                        sc[nt][j] = -1e30f;
                        sc[nt][2 + j] = -1e30f;
                    }
                }
        }
        if (k0 + 127 > row0) {
#pragma unroll
            for (int nt = 0; nt < 16; nt++)
#pragma unroll
                for (int j = 0; j < 2; j++) {
                    int cg = k0 + nt * 8 + tg * 2 + j;
                    if (cg > row0) sc[nt][j] = -1e30f;
                    if (cg > row1) sc[nt][2 + j] = -1e30f;
                }
        }

        float mx0 = -1e30f, mx1 = -1e30f;
#pragma unroll
        for (int nt = 0; nt < 16; nt++) {
            mx0 = fmaxf(mx0, fmaxf(sc[nt][0], sc[nt][1]));
            mx1 = fmaxf(mx1, fmaxf(sc[nt][2], sc[nt][3]));
        }
        mx0 = fmaxf(mx0, __shfl_xor_sync(0xffffffffu, mx0, 1));
        mx0 = fmaxf(mx0, __shfl_xor_sync(0xffffffffu, mx0, 2));
        mx1 = fmaxf(mx1, __shfl_xor_sync(0xffffffffu, mx1, 1));
        mx1 = fmaxf(mx1, __shfl_xor_sync(0xffffffffu, mx1, 2));
        float mn0 = fmaxf(mo0, mx0), mn1 = fmaxf(mo1, mx1);
        float al0 = ex2(mo0 - mn0), al1 = ex2(mo1 - mn1);
        float rs0 = 0.f, rs1 = 0.f;
#pragma unroll
        for (int nt = 0; nt < 16; nt++) {
            sc[nt][0] = ex2(sc[nt][0] - mn0);
            sc[nt][1] = ex2(sc[nt][1] - mn0);
            sc[nt][2] = ex2(sc[nt][2] - mn1);
            sc[nt][3] = ex2(sc[nt][3] - mn1);
            rs0 += sc[nt][0] + sc[nt][1];
            rs1 += sc[nt][2] + sc[nt][3];
        }
        rs0 += __shfl_xor_sync(0xffffffffu, rs0, 1);
        rs0 += __shfl_xor_sync(0xffffffffu, rs0, 2);
        rs1 += __shfl_xor_sync(0xffffffffu, rs1, 1);
        rs1 += __shfl_xor_sync(0xffffffffu, rs1, 2);
        l0 = l0 * al0 + rs0;
        l1 = l1 * al1 + rs1;
        mo0 = mn0; mo1 = mn1;
#pragma unroll
        for (int nt = 0; nt < 8; nt++) {
            oacc[nt][0] *= al0; oacc[nt][1] *= al0;
            oacc[nt][2] *= al1; oacc[nt][3] *= al1;
        }

#pragma unroll
        for (int ks = 0; ks < 8; ks++) {
            uint32_t pa[4], pl[4];
            split2(sc[2 * ks][0], sc[2 * ks][1], pa[0], pl[0]);
            split2(sc[2 * ks][2], sc[2 * ks][3], pa[1], pl[1]);
            split2(sc[2 * ks + 1][0], sc[2 * ks + 1][1], pa[2], pl[2]);
            split2(sc[2 * ks + 1][2], sc[2 * ks + 1][3], pa[3], pl[3]);
#pragma unroll
            for (int dtp = 0; dtp < 4; dtp++) {
                uint32_t vh[4], vl[4];
                int rkv = ks * 16 + ((lane >> 3) & 1) * 8 + (lane & 7);
                int cd = dtp * 16 + (lane >> 4) * 8;
                uint32_t off = (uint32_t)(rkv * 144 + cd * 2);
                ldmatrix_x4_trans(vh, bufb + 36864 + off);
                ldmatrix_x4_trans(vl, bufb + 55296 + off);
#pragma unroll
                for (int hf = 0; hf < 2; hf++)
                    mma16816(oacc[2 * dtp + hf], pa, vh + 2 * hf);
#pragma unroll
                for (int hf = 0; hf < 2; hf++)
                    mma16816(oacc[2 * dtp + hf], pa, vl + 2 * hf);
#pragma unroll
                for (int hf = 0; hf < 2; hf++)
                    mma16816(oacc[2 * dtp + hf], pl, vh + 2 * hf);
            }
        }
    }

    // epilogue: write ctx as single fp16 [B, S, H*D]
    float inv0 = 1.0f / l0, inv1 = 1.0f / l1;
    __half* d0 = g_ch + ((size_t)(bb * S_LEN + row0)) * E_DIM + hh * 64;
    __half* d1 = g_ch + ((size_t)(bb * S_LEN + row1)) * E_DIM + hh * 64;
#pragma unroll
    for (int nt = 0; nt < 8; nt++) {
        int d = nt * 8 + tg * 2;
        __half2 h0 = __floats2half2_rn(oacc[nt][0] * inv0, oacc[nt][1] * inv0);
        __half2 h1 = __floats2half2_rn(oacc[nt][2] * inv1, oacc[nt][3] * inv1);
        *(__half2*)(d0 + d) = h0;
        *(__half2*)(d1 + d) = h1;
    }
}

// ---------------------------------------------------------------------------
extern "C" void kernel_launch(void* const* d_in, const int* in_sizes, int n_in,
                              void* d_out, int out_size) {
    const float* x    = (const float*)d_in[0];
    const int*   mask = (const int*)d_in[1];
    const float* Wq   = (const float*)d_in[2];
    const float* bq   = (const float*)d_in[3];
    const float* Wk   = (const float*)d_in[4];
    const float* bk   = (const float*)d_in[5];
    const float* Wv   = (const float*)d_in[6];
    const float* bv   = (const float*)d_in[7];
    const float* Wo   = (const float*)d_in[8];
    const float* bo   = (const float*)d_in[9];
    float* out = (float*)d_out;

    // weight transpose first (independent; warms L2 before the QKV GEMM)
    cvt_transpose4_kernel<<<dim3(32, 32, 4), 256>>>(Wq, Wk, Wv, Wo);

    rope_table_kernel<<<(S_LEN * 32 + 255) / 256, 256>>>(bq, bk, bv);

    const int n4 = M_ROWS * E_DIM / 4;
    cvt_half_kernel<<<(n4 + 255) / 256, 256>>>((const float4*)x, n4);

    cudaFuncSetAttribute(tgemm_qkv_kernel, cudaFuncAttributeMaxDynamicSharedMemorySize, GSMEM);
    cudaFuncSetAttribute(tgemm_out_kernel, cudaFuncAttributeMaxDynamicSharedMemorySize, GSMEM);
    cudaFuncSetAttribute(attn_kernel, cudaFuncAttributeMaxDynamicSharedMemorySize, ATT_SMEM);

    tgemm_qkv_kernel<<<dim3(E_DIM / 128, M_ROWS / 256, 3), 256, GSMEM>>>();

    attn_kernel<<<dim3(S_LEN / 128, BATCH * N_HEADS), 256, ATT_SMEM>>>(mask);

    tgemm_out_kernel<<<dim3(E_DIM / 128, M_ROWS / 256), 256, GSMEM>>>(bo, out);
}

// round 13
// speedup vs baseline: 2.3567x; 1.0830x over previous
#include <cuda_runtime.h>
#include <cuda_bf16.h>
#include <cuda_fp16.h>
#include <math.h>
#include <stdint.h>

#define S_LEN 2048
#define E_DIM 1024
#define N_HEADS 16
#define HD 64
#define BATCH 2
#define M_ROWS 4096
#define SCALE_Q 0.18033688011112042f   // 0.125 * log2(e)

// ---------------- scratch ---------------------------------------------------
__device__ __align__(256) float g_cos[S_LEN * 32];
__device__ __align__(256) float g_sin[S_LEN * 32];
__device__ __align__(256) float g_bias[3 * E_DIM];
__device__ __align__(256) __half g_xh[(size_t)M_ROWS * E_DIM];          // x fp16
__device__ __align__(256) __half g_ch[(size_t)M_ROWS * E_DIM];          // ctx fp16
__device__ __align__(256) __half g_wth[4][(size_t)E_DIM * E_DIM];       // W^T hi
__device__ __align__(256) __half g_wtl[4][(size_t)E_DIM * E_DIM];       // W^T lo
__device__ __align__(256) __half g_qh2[(size_t)M_ROWS * E_DIM];         // Q hi
__device__ __align__(256) __half g_ql2[(size_t)M_ROWS * E_DIM];         // Q lo
__device__ __align__(256) __half g_kh2[(size_t)M_ROWS * E_DIM];         // K hi
__device__ __align__(256) __half g_kl2[(size_t)M_ROWS * E_DIM];         // K lo
__device__ __align__(256) __half g_vh2[(size_t)M_ROWS * E_DIM];         // V single

// ---------------- helpers ---------------------------------------------------
__device__ __forceinline__ uint32_t smem_u32(const void* p) {
    uint32_t a;
    asm("{ .reg .u64 t; cvta.to.shared.u64 t, %1; cvt.u32.u64 %0, t; }"
        : "=r"(a) : "l"(p));
    return a;
}
__device__ __forceinline__ void ldmatrix_x4(uint32_t* r, uint32_t addr) {
    asm volatile("ldmatrix.sync.aligned.m8n8.x4.shared.b16 {%0,%1,%2,%3}, [%4];"
                 : "=r"(r[0]), "=r"(r[1]), "=r"(r[2]), "=r"(r[3]) : "r"(addr));
}
__device__ __forceinline__ void ldmatrix_x4_trans(uint32_t* r, uint32_t addr) {
    asm volatile("ldmatrix.sync.aligned.m8n8.x4.trans.shared.b16 {%0,%1,%2,%3}, [%4];"
                 : "=r"(r[0]), "=r"(r[1]), "=r"(r[2]), "=r"(r[3]) : "r"(addr));
}
__device__ __forceinline__ void mma16816h(float* c, const uint32_t* a, const uint32_t* b) {
    asm("mma.sync.aligned.m16n8k16.row.col.f32.f16.f16.f32 "
        "{%0,%1,%2,%3}, {%4,%5,%6,%7}, {%8,%9}, {%0,%1,%2,%3};"
        : "+f"(c[0]), "+f"(c[1]), "+f"(c[2]), "+f"(c[3])
        : "r"(a[0]), "r"(a[1]), "r"(a[2]), "r"(a[3]), "r"(b[0]), "r"(b[1]));
}
__device__ __forceinline__ void cp_async16(uint32_t dst, const void* src) {
    asm volatile("cp.async.cg.shared.global [%0], [%1], 16;" :: "r"(dst), "l"(src));
}
__device__ __forceinline__ float ex2(float x) {
    float y;
    asm("ex2.approx.f32 %0, %1;" : "=f"(y) : "f"(x));
    return y;
}
// fp16 hi/lo split of a float pair
__device__ __forceinline__ void split2h(float x, float y, uint32_t& h, uint32_t& l) {
    __half2 hb = __floats2half2_rn(x, y);
    float2 hf = __half22float2(hb);
    __half2 lb = __floats2half2_rn(x - hf.x, y - hf.y);
    h = *(uint32_t*)&hb;
    l = *(uint32_t*)&lb;
}

// ---------------------------------------------------------------------------
__global__ void rope_table_kernel(const float* __restrict__ bq,
                                  const float* __restrict__ bk,
                                  const float* __restrict__ bv) {
    int i = blockIdx.x * blockDim.x + threadIdx.x;
    if (i < 3 * E_DIM) {
        const float* b = (i < E_DIM) ? bq : (i < 2 * E_DIM) ? bk : bv;
        g_bias[i] = b[i & (E_DIM - 1)];
    }
    if (i >= S_LEN * 32) return;
    int s = i >> 5, j = i & 31;
    float inv = (float)pow(10000.0, -(double)j / 32.0);
    float th = (float)s * inv;
    g_cos[i] = cosf(th);
    g_sin[i] = sinf(th);
}

__global__ void cvt_half_kernel(const float4* __restrict__ src, int n4) {
    int i = blockIdx.x * blockDim.x + threadIdx.x;
    if (i >= n4) return;
    float4 v = src[i];
    __half2* dst = (__half2*)g_xh;
    dst[2 * i]     = __floats2half2_rn(v.x, v.y);
    dst[2 * i + 1] = __floats2half2_rn(v.z, v.w);
}

__global__ void cvt_transpose4_kernel(const float* __restrict__ W0,
                                      const float* __restrict__ W1,
                                      const float* __restrict__ W2,
                                      const float* __restrict__ W3) {
    __shared__ float t[32][33];
    const float* Ws[4] = {W0, W1, W2, W3};
    const float* W = Ws[blockIdx.z];
    __half* th = g_wth[blockIdx.z];
    __half* tl = g_wtl[blockIdx.z];
    int bx = blockIdx.x, by = blockIdx.y;
    int tid = threadIdx.x;
#pragma unroll
    for (int it = 0; it < 4; it++) {
        int idx = tid + it * 256;
        int r = idx >> 5, c = idx & 31;
        t[r][c] = W[(size_t)(by * 32 + r) * E_DIM + bx * 32 + c];
    }
    __syncthreads();
#pragma unroll
    for (int it = 0; it < 4; it++) {
        int idx = tid + it * 256;
        int r = idx >> 5, c = idx & 31;
        float x = t[c][r];
        __half h = __float2half_rn(x);
        size_t o = (size_t)(bx * 32 + r) * E_DIM + by * 32 + c;
        th[o] = h;
        tl[o] = __float2half_rn(x - __half2float(h));
    }
}

// ---------------------------------------------------------------------------
// 2-term fp16 GEMM: C = A * (Bhi + Blo). CTA 256x128, BK=64, 8 warps (4x2).
// ---------------------------------------------------------------------------
#define A_TB 36864
#define B_TB 18432
#define BUF_BYTES (A_TB + 2 * B_TB)
#define GSMEM (2 * BUF_BYTES)
#define NCHUNK 16

__device__ __forceinline__ void load_chunk_async(
    const __half* __restrict__ A,
    const __half* __restrict__ Bhi, const __half* __restrict__ Blo,
    int m0, int n0, int k0, uint32_t st, int tid) {
#pragma unroll
    for (int it = 0; it < 8; it++) {
        int idx = tid + it * 256;
        int r = idx >> 3, seg = idx & 7;
        cp_async16(st + (uint32_t)(r * 144 + seg * 16),
                   A + (size_t)(m0 + r) * E_DIM + k0 + seg * 8);
    }
#pragma unroll
    for (int it = 0; it < 4; it++) {
        int idx = tid + it * 256;
        int r = idx >> 3, seg = idx & 7;
        uint32_t off = (uint32_t)(r * 144 + seg * 16);
        const size_t go = (size_t)(n0 + r) * E_DIM + k0 + seg * 8;
        cp_async16(st + A_TB + off, Bhi + go);
        cp_async16(st + A_TB + B_TB + off, Blo + go);
    }
}

__device__ __forceinline__ void gemm_mainloop(
    const __half* __restrict__ A,
    const __half* __restrict__ Bhi, const __half* __restrict__ Blo,
    int m0, int n0, uint32_t sbase, int tid, int wm, int wn, int lane,
    float acc[4][8][4]) {

    load_chunk_async(A, Bhi, Blo, m0, n0, 0, sbase, tid);
    asm volatile("cp.async.commit_group;");

    for (int c = 0; c < NCHUNK; c++) {
        asm volatile("cp.async.wait_group 0;");
        __syncthreads();
        if (c + 1 < NCHUNK) {
            load_chunk_async(A, Bhi, Blo, m0, n0, (c + 1) << 6,
                             sbase + ((c + 1) & 1) * BUF_BYTES, tid);
            asm volatile("cp.async.commit_group;");
        }

        const uint32_t st = sbase + (c & 1) * BUF_BYTES;
        const uint32_t A_s = st;
        const uint32_t Bhi_s = st + A_TB, Blo_s = st + A_TB + B_TB;

#pragma unroll
        for (int ks = 0; ks < 4; ks++) {
            uint32_t af[4][4];
#pragma unroll
            for (int mt = 0; mt < 4; mt++) {
                int row = wm * 64 + mt * 16 + (lane & 15);
                int kb = ks * 16 + ((lane >> 4) << 3);
                ldmatrix_x4(af[mt], A_s + (uint32_t)(row * 144 + kb * 2));
            }
#pragma unroll
            for (int np = 0; np < 4; np++) {
                uint32_t bh[4], bl[4];
                int row = wn * 64 + np * 16 + ((lane >> 4) << 3) + (lane & 7);
                int kb = ks * 16 + (((lane >> 3) & 1) << 3);
                uint32_t off = (uint32_t)(row * 144 + kb * 2);
                ldmatrix_x4(bh, Bhi_s + off);
                ldmatrix_x4(bl, Blo_s + off);
#pragma unroll
                for (int half = 0; half < 2; half++)
#pragma unroll
                    for (int mt = 0; mt < 4; mt++)
                        mma16816h(acc[mt][2 * np + half], af[mt], bh + 2 * half);
#pragma unroll
                for (int half = 0; half < 2; half++)
#pragma unroll
                    for (int mt = 0; mt < 4; mt++)
                        mma16816h(acc[mt][2 * np + half], af[mt], bl + 2 * half);
            }
        }
    }
}

// Fused QKV projection: z = 0:Q(+RoPE+scale, fp16 hi/lo) 1:K(+RoPE, fp16 hi/lo)
//                       2:V(single fp16)
__global__ __launch_bounds__(256)
void tgemm_qkv_kernel() {
    extern __shared__ __align__(1024) char dsm[];
    const uint32_t sbase = smem_u32(dsm);
    const int tid = threadIdx.x;
    const int wid = tid >> 5, lane = tid & 31;
    const int wm = wid & 3, wn = wid >> 2;
    const int g = lane >> 2, tg = lane & 3;
    const int m0 = blockIdx.y << 8, n0 = blockIdx.x << 7;
    const int z = blockIdx.z;

    const float* bias = g_bias + (z << 10);

    float acc[4][8][4] = {};
    gemm_mainloop(g_xh, g_wth[z], g_wtl[z], m0, n0, sbase, tid, wm, wn, lane, acc);

    const int h = (n0 + wn * 64) >> 6;
#pragma unroll
    for (int mt = 0; mt < 4; mt++) {
#pragma unroll
        for (int h2 = 0; h2 < 2; h2++) {
            int m = m0 + wm * 64 + mt * 16 + g + h2 * 8;
            int bb = m >> 11, s = m & (S_LEN - 1);
            size_t rb = (((size_t)(bb * N_HEADS + h)) * S_LEN + s) << 6;
            float vals[8][2];
#pragma unroll
            for (int nt = 0; nt < 8; nt++) {
                int col = nt * 8 + tg * 2;
                float2 bv = *(const float2*)&bias[n0 + wn * 64 + col];
                vals[nt][0] = acc[mt][nt][h2 * 2 + 0] + bv.x;
                vals[nt][1] = acc[mt][nt][h2 * 2 + 1] + bv.y;
            }
            if (z < 2) {
#pragma unroll
                for (int nt = 0; nt < 4; nt++) {
#pragma unroll
                    for (int jj = 0; jj < 2; jj++) {
                        int d = nt * 8 + tg * 2 + jj;
                        float cth = g_cos[(s << 5) + d];
                        float sth = g_sin[(s << 5) + d];
                        float lo = vals[nt][jj], hi = vals[nt + 4][jj];
                        vals[nt][jj]     = fmaf(lo, cth, -hi * sth);
                        vals[nt + 4][jj] = fmaf(hi, cth,  lo * sth);
                    }
                }
            }
            if (z == 0) {
#pragma unroll
                for (int nt = 0; nt < 8; nt++) {
                    vals[nt][0] *= SCALE_Q;
                    vals[nt][1] *= SCALE_Q;
                }
            }
            if (z == 2) {
                // V: single fp16
#pragma unroll
                for (int nt = 0; nt < 8; nt++) {
                    __half2 hv = __floats2half2_rn(vals[nt][0], vals[nt][1]);
                    *(__half2*)(g_vh2 + rb + nt * 8 + tg * 2) = hv;
                }
            } else {
                __half* Chi = (z == 0) ? g_qh2 : g_kh2;
                __half* Clo = (z == 0) ? g_ql2 : g_kl2;
#pragma unroll
                for (int nt = 0; nt < 8; nt++) {
                    uint32_t hv, lv;
                    split2h(vals[nt][0], vals[nt][1], hv, lv);
                    *(uint32_t*)(Chi + rb + nt * 8 + tg * 2) = hv;
                    *(uint32_t*)(Clo + rb + nt * 8 + tg * 2) = lv;
                }
            }
        }
    }
}

// Output projection: out = ctx(fp16) @ (Wohi + Wolo) + bo
__global__ __launch_bounds__(256)
void tgemm_out_kernel(const float* __restrict__ bias, float* __restrict__ C) {
    extern __shared__ __align__(1024) char dsm[];
    const uint32_t sbase = smem_u32(dsm);
    const int tid = threadIdx.x;
    const int wid = tid >> 5, lane = tid & 31;
    const int wm = wid & 3, wn = wid >> 2;
    const int g = lane >> 2, tg = lane & 3;
    const int m0 = blockIdx.y << 8, n0 = blockIdx.x << 7;

    float acc[4][8][4] = {};
    gemm_mainloop(g_ch, g_wth[3], g_wtl[3], m0, n0, sbase, tid, wm, wn, lane, acc);

#pragma unroll
    for (int mt = 0; mt < 4; mt++) {
#pragma unroll
        for (int h2 = 0; h2 < 2; h2++) {
            int m = m0 + wm * 64 + mt * 16 + g + h2 * 8;
            float* dst = &C[(size_t)m * E_DIM + n0 + wn * 64];
#pragma unroll
            for (int nt = 0; nt < 8; nt++) {
                int col = nt * 8 + tg * 2;
                float2 bv = *(const float2*)&bias[n0 + wn * 64 + col];
                *(float2*)&dst[col] = make_float2(acc[mt][nt][h2 * 2 + 0] + bv.x,
                                                  acc[mt][nt][h2 * 2 + 1] + bv.y);
            }
        }
    }
}

// ---------------------------------------------------------------------------
// Flash attention. Q-tile 128, KV-tile 128, 8 warps.
// QK: 3-term fp16 (Q hi/lo hoisted x K hi/lo).  PV: 2-term (P hi/lo regs x V single).
// smem buf: Khi[128][144B] Klo Vs + mask -> 55808 per buffer.
// ---------------------------------------------------------------------------
#define ATT_Q    0
#define ATT_QL   18432
#define ATT_BUF0 36864
#define ATT_BUFSZ 55808                    // 3*18432 + 512
#define ATT_SMEM (36864 + 2 * ATT_BUFSZ)   // 148480

__device__ __forceinline__ void attn_issue_kv(
    const __half* khi, const __half* klo, const __half* v,
    const int* mask, int mask_off, uint32_t sb, int t, int tid) {
    uint32_t bufb = sb + ATT_BUF0 + (t & 1) * ATT_BUFSZ;
    int k0 = t << 7;
    const __half* srcs[3] = {khi, klo, v};
#pragma unroll
    for (int i = 0; i < 12; i++) {
        int idx = tid + i * 256;            // 0..3071
        int arr = idx >> 10;
        int r = (idx >> 3) & 127, seg = idx & 7;
        cp_async16(bufb + arr * 18432 + (uint32_t)(r * 144 + seg * 16),
                   srcs[arr] + (size_t)(k0 + r) * HD + seg * 8);
    }
    if (tid < 32)
        cp_async16(bufb + 55296 + tid * 16, mask + mask_off + k0 + tid * 4);
}

__global__ __launch_bounds__(256)
void attn_kernel(const int* __restrict__ mask) {
    extern __shared__ __align__(1024) char sm_[];
    const uint32_t sb = smem_u32(sm_);
    const int tid = threadIdx.x, w = tid >> 5, lane = tid & 31;
    const int g = lane >> 2, tg = lane & 3;
    const int qt = gridDim.x - 1 - blockIdx.x;
    const int bh = blockIdx.y, bb = bh >> 4, hh = bh & 15;
    const int q0 = qt << 7;
    const size_t base = (size_t)bh * S_LEN * HD;

    // load Q hi/lo (fp16)
    {
        const __half* s0 = g_qh2 + base + (size_t)q0 * HD;
        const __half* s1 = g_ql2 + base + (size_t)q0 * HD;
#pragma unroll
        for (int i = 0; i < 8; i++) {
            int idx = tid + i * 256;
            int arr = idx >> 10;
            int r = (idx >> 3) & 127, seg = idx & 7;
            uint4 v = *(const uint4*)((arr ? s1 : s0) + (size_t)r * HD + seg * 8);
            *(uint4*)(sm_ + (arr ? ATT_QL : ATT_Q) + r * 144 + seg * 16) = v;
        }
    }

    const int ntile = qt + 1;
    attn_issue_kv(g_kh2 + base, g_kl2 + base, g_vh2 + base,
                  mask, bb * S_LEN, sb, 0, tid);
    asm volatile("cp.async.commit_group;");
    __syncthreads();

    uint32_t qfh[4][4], qfl[4][4];
    {
        int i = lane & 15;
        int prow = (i < 8) ? (w * 8 + i) : (64 + w * 8 + (i - 8));
        int kb = ((lane >> 4) << 3);
#pragma unroll
        for (int ks = 0; ks < 4; ks++) {
            uint32_t off = (uint32_t)(prow * 144 + (ks * 16 + kb) * 2);
            ldmatrix_x4(qfh[ks], sb + ATT_Q + off);
            ldmatrix_x4(qfl[ks], sb + ATT_QL + off);
        }
    }
    const int row0 = q0 + w * 8 + g;
    const int row1 = q0 + 64 + w * 8 + g;

    float oacc[8][4] = {};
    float l0 = 0.f, l1 = 0.f, mo0 = -1e30f, mo1 = -1e30f;

    for (int t = 0; t < ntile; t++) {
        asm volatile("cp.async.wait_group 0;");
        __syncthreads();
        if (t + 1 < ntile) {
            attn_issue_kv(g_kh2 + base, g_kl2 + base, g_vh2 + base,
                          mask, bb * S_LEN, sb, t + 1, tid);
            asm volatile("cp.async.commit_group;");
        }
        const uint32_t bufb = sb + ATT_BUF0 + (t & 1) * ATT_BUFSZ;
        const int k0 = t << 7;

        // S = Q @ K^T  (3 terms: Qhi*Khi + Qhi*Klo + Qlo*Khi)
        float sc[16][4] = {};
#pragma unroll
        for (int ks = 0; ks < 4; ks++) {
#pragma unroll
            for (int ntp = 0; ntp < 8; ntp++) {
                uint32_t kh[4], kl[4];
                int row = ntp * 16 + ((lane >> 4) << 3) + (lane & 7);
                int kb = ks * 16 + (((lane >> 3) & 1) << 3);
                uint32_t off = (uint32_t)(row * 144 + kb * 2);
                ldmatrix_x4(kh, bufb + off);
                ldmatrix_x4(kl, bufb + 18432 + off);
#pragma unroll
                for (int hf = 0; hf < 2; hf++)
                    mma16816h(sc[2 * ntp + hf], qfh[ks], kh + 2 * hf);
#pragma unroll
                for (int hf = 0; hf < 2; hf++)
                    mma16816h(sc[2 * ntp + hf], qfh[ks], kl + 2 * hf);
#pragma unroll
                for (int hf = 0; hf < 2; hf++)
                    mma16816h(sc[2 * ntp + hf], qfl[ks], kh + 2 * hf);
            }
        }

        const int* Ms = (const int*)(sm_ + ATT_BUF0 + (t & 1) * ATT_BUFSZ + 55296);
        uint32_t pb[4];
        pb[0] = __ballot_sync(0xffffffffu, Ms[lane] != 0);
        pb[1] = __ballot_sync(0xffffffffu, Ms[lane + 32] != 0);
        pb[2] = __ballot_sync(0xffffffffu, Ms[lane + 64] != 0);
        pb[3] = __ballot_sync(0xffffffffu, Ms[lane + 96] != 0);
        if ((pb[0] & pb[1] & pb[2] & pb[3]) != 0xffffffffu) {
#pragma unroll
            for (int nt = 0; nt < 16; nt++)
#pragma unroll
                for (int j = 0; j < 2; j++) {
                    int cl = nt * 8 + tg * 2 + j;
                    if (!((pb[cl >> 5] >> (cl & 31)) & 1)) {
                        sc[nt][j] = -1e30f;
                        sc[nt][2 + j] = -1e30f;
                    }
                }
        }
        if (k0 + 127 > row0) {
#pragma unroll
            for (int nt = 0; nt < 16; nt++)
#pragma unroll
                for (int j = 0; j < 2; j++) {
                    int cg = k0 + nt * 8 + tg * 2 + j;
                    if (cg > row0) sc[nt][j] = -1e30f;
                    if (cg > row1) sc[nt][2 + j] = -1e30f;
                }
        }

        float mx0 = -1e30f, mx1 = -1e30f;
#pragma unroll
        for (int nt = 0; nt < 16; nt++) {
            mx0 = fmaxf(mx0, fmaxf(sc[nt][0], sc[nt][1]));
            mx1 = fmaxf(mx1, fmaxf(sc[nt][2], sc[nt][3]));
        }
        mx0 = fmaxf(mx0, __shfl_xor_sync(0xffffffffu, mx0, 1));
        mx0 = fmaxf(mx0, __shfl_xor_sync(0xffffffffu, mx0, 2));
        mx1 = fmaxf(mx1, __shfl_xor_sync(0xffffffffu, mx1, 1));
        mx1 = fmaxf(mx1, __shfl_xor_sync(0xffffffffu, mx1, 2));
        float mn0 = fmaxf(mo0, mx0), mn1 = fmaxf(mo1, mx1);
        float al0 = ex2(mo0 - mn0), al1 = ex2(mo1 - mn1);
        float rs0 = 0.f, rs1 = 0.f;
#pragma unroll
        for (int nt = 0; nt < 16; nt++) {
            sc[nt][0] = ex2(sc[nt][0] - mn0);
            sc[nt][1] = ex2(sc[nt][1] - mn0);
            sc[nt][2] = ex2(sc[nt][2] - mn1);
            sc[nt][3] = ex2(sc[nt][3] - mn1);
            rs0 += sc[nt][0] + sc[nt][1];
            rs1 += sc[nt][2] + sc[nt][3];
        }
        rs0 += __shfl_xor_sync(0xffffffffu, rs0, 1);
        rs0 += __shfl_xor_sync(0xffffffffu, rs0, 2);
        rs1 += __shfl_xor_sync(0xffffffffu, rs1, 1);
        rs1 += __shfl_xor_sync(0xffffffffu, rs1, 2);
        l0 = l0 * al0 + rs0;
        l1 = l1 * al1 + rs1;
        mo0 = mn0; mo1 = mn1;
#pragma unroll
        for (int nt = 0; nt < 8; nt++) {
            oacc[nt][0] *= al0; oacc[nt][1] *= al0;
            oacc[nt][2] *= al1; oacc[nt][3] *= al1;
        }

        // O += (Phi + Plo) @ V   (V single fp16)
#pragma unroll
        for (int ks = 0; ks < 8; ks++) {
            uint32_t pa[4], pl[4];
            split2h(sc[2 * ks][0], sc[2 * ks][1], pa[0], pl[0]);
            split2h(sc[2 * ks][2], sc[2 * ks][3], pa[1], pl[1]);
            split2h(sc[2 * ks + 1][0], sc[2 * ks + 1][1], pa[2], pl[2]);
            split2h(sc[2 * ks + 1][2], sc[2 * ks + 1][3], pa[3], pl[3]);
#pragma unroll
            for (int dtp = 0; dtp < 4; dtp++) {
                uint32_t vh[4];
                int rkv = ks * 16 + ((lane >> 3) & 1) * 8 + (lane & 7);
                int cd = dtp * 16 + (lane >> 4) * 8;
                ldmatrix_x4_trans(vh, bufb + 36864 + (uint32_t)(rkv * 144 + cd * 2));
#pragma unroll
                for (int hf = 0; hf < 2; hf++)
                    mma16816h(oacc[2 * dtp + hf], pa, vh + 2 * hf);
#pragma unroll
                for (int hf = 0; hf < 2; hf++)
                    mma16816h(oacc[2 * dtp + hf], pl, vh + 2 * hf);
            }
        }
    }

    // epilogue: ctx single fp16
    float inv0 = 1.0f / l0, inv1 = 1.0f / l1;
    __half* d0 = g_ch + ((size_t)(bb * S_LEN + row0)) * E_DIM + hh * 64;
    __half* d1 = g_ch + ((size_t)(bb * S_LEN + row1)) * E_DIM + hh * 64;
#pragma unroll
    for (int nt = 0; nt < 8; nt++) {
        int d = nt * 8 + tg * 2;
        *(__half2*)(d0 + d) = __floats2half2_rn(oacc[nt][0] * inv0, oacc[nt][1] * inv0);
        *(__half2*)(d1 + d) = __floats2half2_rn(oacc[nt][2] * inv1, oacc[nt][3] * inv1);
    }
}

// ---------------------------------------------------------------------------
extern "C" void kernel_launch(void* const* d_in, const int* in_sizes, int n_in,
                              void* d_out, int out_size) {
    const float* x    = (const float*)d_in[0];
    const int*   mask = (const int*)d_in[1];
    const float* Wq   = (const float*)d_in[2];
    const float* bq   = (const float*)d_in[3];
    const float* Wk   = (const float*)d_in[4];
    const float* bk   = (const float*)d_in[5];
    const float* Wv   = (const float*)d_in[6];
    const float* bv   = (const float*)d_in[7];
    const float* Wo   = (const float*)d_in[8];
    const float* bo   = (const float*)d_in[9];
    float* out = (float*)d_out;

    cvt_transpose4_kernel<<<dim3(32, 32, 4), 256>>>(Wq, Wk, Wv, Wo);

    rope_table_kernel<<<(S_LEN * 32 + 255) / 256, 256>>>(bq, bk, bv);

    const int n4 = M_ROWS * E_DIM / 4;
    cvt_half_kernel<<<(n4 + 255) / 256, 256>>>((const float4*)x, n4);

    cudaFuncSetAttribute(tgemm_qkv_kernel, cudaFuncAttributeMaxDynamicSharedMemorySize, GSMEM);
    cudaFuncSetAttribute(tgemm_out_kernel, cudaFuncAttributeMaxDynamicSharedMemorySize, GSMEM);
    cudaFuncSetAttribute(attn_kernel, cudaFuncAttributeMaxDynamicSharedMemorySize, ATT_SMEM);

    tgemm_qkv_kernel<<<dim3(E_DIM / 128, M_ROWS / 256, 3), 256, GSMEM>>>();

    attn_kernel<<<dim3(S_LEN / 128, BATCH * N_HEADS), 256, ATT_SMEM>>>(mask);

    tgemm_out_kernel<<<dim3(E_DIM / 128, M_ROWS / 256), 256, GSMEM>>>(bo, out);
}